// round 1
// baseline (speedup 1.0000x reference)
#include <cuda_runtime.h>
#include <math.h>

// ---------------- problem constants ----------------
#define BB 4
#define NN 1024
#define DDIM 1024
#define HH 16
#define DHEAD 64
#define CTXN 77
#define CTXD 768
#define FFIN 8192
#define FFHID 4096
#define TOK (BB*NN)      // 4096
#define CTOK (BB*CTXN)   // 308
#define SCALE 0.125f     // 64^-0.5

// ---------------- scratch (device globals; no allocation allowed) ----------------
__device__ float g_ln[(size_t)TOK*DDIM];
__device__ float g_q [(size_t)TOK*DDIM];
__device__ float g_k [(size_t)TOK*DDIM];
__device__ float g_v [(size_t)TOK*DDIM];
__device__ float g_ao[(size_t)TOK*DDIM];
// big buffer: attn scores (64M floats) -- also reused for FF hidden (32M) + act (16M)
__device__ float g_sim[(size_t)BB*HH*NN*NN];

// ---------------- LayerNorm: one block per row of 1024 ----------------
__global__ void __launch_bounds__(256) ln_kernel(const float* __restrict__ x,
    const float* __restrict__ w, const float* __restrict__ b, float* __restrict__ out)
{
    int row = blockIdx.x;
    int t = threadIdx.x;
    const float4* xr = (const float4*)(x + (size_t)row * DDIM);
    float4 v = xr[t];
    float s  = v.x + v.y + v.z + v.w;
    float ss = v.x*v.x + v.y*v.y + v.z*v.z + v.w*v.w;
    #pragma unroll
    for (int o = 16; o; o >>= 1) {
        s  += __shfl_xor_sync(0xffffffffu, s, o);
        ss += __shfl_xor_sync(0xffffffffu, ss, o);
    }
    __shared__ float sh_s[8], sh_q[8];
    int wid = t >> 5, lane = t & 31;
    if (lane == 0) { sh_s[wid] = s; sh_q[wid] = ss; }
    __syncthreads();
    if (t == 0) {
        float a = 0.f, c = 0.f;
        #pragma unroll
        for (int i = 0; i < 8; i++) { a += sh_s[i]; c += sh_q[i]; }
        float m = a * (1.0f/DDIM);
        float var = c * (1.0f/DDIM) - m*m;
        sh_s[0] = m;
        sh_q[0] = rsqrtf(var + 1e-5f);
    }
    __syncthreads();
    float m = sh_s[0], r = sh_q[0];
    float4 wv = ((const float4*)w)[t];
    float4 bv = ((const float4*)b)[t];
    float4 o4;
    o4.x = (v.x - m) * r * wv.x + bv.x;
    o4.y = (v.y - m) * r * wv.y + bv.y;
    o4.z = (v.z - m) * r * wv.z + bv.z;
    o4.w = (v.w - m) * r * wv.w + bv.w;
    ((float4*)(out + (size_t)row * DDIM))[t] = o4;
}

// ---------------- SGEMM: C[M,N] = A[M,K] @ W[K,N] + epilogue ----------------
// MODE 0: fake-quant (zp=128): clip(rint(x/d), -128, 127)*d
// MODE 1: + bias[n] + res[m,n]
// MODE 2: + bias[n]
template<int MODE>
__global__ void __launch_bounds__(256) sgemm_k(
    const float* __restrict__ A, const float* __restrict__ W,
    const float* __restrict__ bias, const float* __restrict__ res,
    float* __restrict__ C, int M, int N, int K, const float* __restrict__ dptr)
{
    __shared__ float As[8][128];
    __shared__ float Bs[8][128];
    const int tid  = threadIdx.x;
    const int crow = blockIdx.y * 128;
    const int ccol = blockIdx.x * 128;

    const int arow = tid >> 1;        // 0..127
    const int acol = (tid & 1) * 4;   // 0 or 4
    const int brow = tid >> 5;        // 0..7
    const int bcol = (tid & 31) * 4;  // 0..124

    const int tr = (tid >> 4) * 8;
    const int tc = (tid & 15) * 8;

    float acc[8][8];
    #pragma unroll
    for (int i = 0; i < 8; i++)
        #pragma unroll
        for (int j = 0; j < 8; j++) acc[i][j] = 0.f;

    for (int k0 = 0; k0 < K; k0 += 8) {
        float4 a4 = make_float4(0.f, 0.f, 0.f, 0.f);
        int gr = crow + arow;
        if (gr < M) a4 = *(const float4*)(A + (size_t)gr * K + k0 + acol);
        As[acol+0][arow] = a4.x;
        As[acol+1][arow] = a4.y;
        As[acol+2][arow] = a4.z;
        As[acol+3][arow] = a4.w;
        float4 b4 = *(const float4*)(W + (size_t)(k0 + brow) * N + ccol + bcol);
        *(float4*)&Bs[brow][bcol] = b4;
        __syncthreads();
        #pragma unroll
        for (int kk = 0; kk < 8; kk++) {
            float4 ra0 = *(float4*)&As[kk][tr];
            float4 ra1 = *(float4*)&As[kk][tr+4];
            float4 rb0 = *(float4*)&Bs[kk][tc];
            float4 rb1 = *(float4*)&Bs[kk][tc+4];
            float ra[8] = {ra0.x, ra0.y, ra0.z, ra0.w, ra1.x, ra1.y, ra1.z, ra1.w};
            float rb[8] = {rb0.x, rb0.y, rb0.z, rb0.w, rb1.x, rb1.y, rb1.z, rb1.w};
            #pragma unroll
            for (int i = 0; i < 8; i++)
                #pragma unroll
                for (int j = 0; j < 8; j++) acc[i][j] += ra[i] * rb[j];
        }
        __syncthreads();
    }

    float d = 0.f, invd = 0.f;
    if (MODE == 0) { d = *dptr; invd = 1.0f / d; }
    #pragma unroll
    for (int i = 0; i < 8; i++) {
        int r = crow + tr + i;
        if (r >= M) continue;
        #pragma unroll
        for (int j = 0; j < 8; j++) {
            int c = ccol + tc + j;
            float v = acc[i][j];
            if (MODE == 0) {
                v = fminf(fmaxf(rintf(v * invd), -128.f), 127.f) * d;
            } else if (MODE == 1) {
                v = v + bias[c] + res[(size_t)r * N + c];
            } else {
                v = v + bias[c];
            }
            C[(size_t)r * N + c] = v;
        }
    }
}

// ---------------- batched scores: S[bh,i,j] = scale * q . k, K=64 ----------------
__global__ void __launch_bounds__(256) sim_kernel(
    const float* __restrict__ Q, const float* __restrict__ Km,
    float* __restrict__ S, int nk)
{
    int bh = blockIdx.z; int b = bh >> 4; int h = bh & 15;
    int i0 = blockIdx.y * 64;
    int j0 = blockIdx.x * 64;
    __shared__ float qs[64][65];  // [dh][i]
    __shared__ float ks[64][65];  // [dh][j]
    int tid = threadIdx.x;
    const float* qbase = Q + ((size_t)(b * NN + i0)) * DDIM + h * 64;
    const float* kbase = Km + ((size_t)b * nk) * DDIM + h * 64;
    #pragma unroll
    for (int it = 0; it < 4; it++) {
        int idx = tid + it * 256;
        int r = idx >> 4;
        int c = (idx & 15) * 4;
        float4 qv = *(const float4*)(qbase + (size_t)r * DDIM + c);
        qs[c+0][r] = qv.x; qs[c+1][r] = qv.y; qs[c+2][r] = qv.z; qs[c+3][r] = qv.w;
        int jr = j0 + r;
        float4 kv = make_float4(0.f, 0.f, 0.f, 0.f);
        if (jr < nk) kv = *(const float4*)(kbase + (size_t)jr * DDIM + c);
        ks[c+0][r] = kv.x; ks[c+1][r] = kv.y; ks[c+2][r] = kv.z; ks[c+3][r] = kv.w;
    }
    __syncthreads();
    int ty = tid >> 4, tx = tid & 15;
    float acc[4][4];
    #pragma unroll
    for (int i = 0; i < 4; i++)
        #pragma unroll
        for (int j = 0; j < 4; j++) acc[i][j] = 0.f;
    #pragma unroll
    for (int kk = 0; kk < 64; kk++) {
        float ra[4], rb[4];
        #pragma unroll
        for (int i = 0; i < 4; i++) ra[i] = qs[kk][ty*4+i];
        #pragma unroll
        for (int j = 0; j < 4; j++) rb[j] = ks[kk][tx*4+j];
        #pragma unroll
        for (int i = 0; i < 4; i++)
            #pragma unroll
            for (int j = 0; j < 4; j++) acc[i][j] += ra[i] * rb[j];
    }
    #pragma unroll
    for (int i = 0; i < 4; i++) {
        size_t rowoff = ((size_t)bh * NN + i0 + ty*4 + i) * nk;
        #pragma unroll
        for (int j = 0; j < 4; j++) {
            int jj = j0 + tx*4 + j;
            if (jj < nk) S[rowoff + jj] = acc[i][j] * SCALE;
        }
    }
}

// ---------------- softmax over last dim + weight fake-quant (zp=0) ----------------
__global__ void __launch_bounds__(128) softmax_quant(float* __restrict__ S, int cols,
                                                     const float* __restrict__ dptr)
{
    size_t row = blockIdx.x;
    float* p = S + row * (size_t)cols;
    int t = threadIdx.x;
    float buf[8];
    int nb = 0;
    float m = -INFINITY;
    for (int c = t; c < cols; c += 128) {
        float v = p[c];
        buf[nb++] = v;
        m = fmaxf(m, v);
    }
    #pragma unroll
    for (int o = 16; o; o >>= 1) m = fmaxf(m, __shfl_xor_sync(0xffffffffu, m, o));
    __shared__ float redm[4], reds[4];
    if ((t & 31) == 0) redm[t >> 5] = m;
    __syncthreads();
    m = fmaxf(fmaxf(redm[0], redm[1]), fmaxf(redm[2], redm[3]));
    float sum = 0.f;
    for (int i = 0; i < nb; i++) { buf[i] = expf(buf[i] - m); sum += buf[i]; }
    #pragma unroll
    for (int o = 16; o; o >>= 1) sum += __shfl_xor_sync(0xffffffffu, sum, o);
    if ((t & 31) == 0) reds[t >> 5] = sum;
    __syncthreads();
    sum = reds[0] + reds[1] + reds[2] + reds[3];
    float inv = 1.0f / sum;
    float d = *dptr;
    float invd = 1.0f / d;
    nb = 0;
    for (int c = t; c < cols; c += 128) {
        float q = rintf(buf[nb++] * inv * invd);
        q = fminf(fmaxf(q, 0.f), 255.f);
        p[c] = q * d;
    }
}

// ---------------- batched AV: O[bh,i,dh] = sum_j aw * v ----------------
__global__ void __launch_bounds__(256) av_kernel(
    const float* __restrict__ Aw, const float* __restrict__ V,
    float* __restrict__ O, int nk)
{
    int bh = blockIdx.y; int b = bh >> 4; int h = bh & 15;
    int i0 = blockIdx.x * 64;
    __shared__ float as[64][65];  // [j][i]
    __shared__ float vs[64][68];  // [j][dh]
    int tid = threadIdx.x;
    int ty = tid >> 4, tx = tid & 15;
    float acc[4][4];
    #pragma unroll
    for (int i = 0; i < 4; i++)
        #pragma unroll
        for (int j = 0; j < 4; j++) acc[i][j] = 0.f;
    const float* arow  = Aw + ((size_t)bh * NN + i0) * nk;
    const float* vbase = V + ((size_t)b * nk) * DDIM + h * 64;

    for (int j0 = 0; j0 < nk; j0 += 64) {
        #pragma unroll
        for (int it = 0; it < 4; it++) {
            int idx = tid + it * 256;
            int r = idx >> 4;         // i
            int c = (idx & 15) * 4;   // j
            #pragma unroll
            for (int mloc = 0; mloc < 4; mloc++) {
                int jj = j0 + c + mloc;
                as[c + mloc][r] = (jj < nk) ? arow[(size_t)r * nk + jj] : 0.f;
            }
            int jr = j0 + r;          // j for v
            float4 vv = make_float4(0.f, 0.f, 0.f, 0.f);
            if (jr < nk) vv = *(const float4*)(vbase + (size_t)jr * DDIM + c);
            *(float4*)&vs[r][c] = vv;
        }
        __syncthreads();
        #pragma unroll
        for (int kk = 0; kk < 64; kk++) {
            float ra[4], rb[4];
            #pragma unroll
            for (int i = 0; i < 4; i++) ra[i] = as[kk][ty*4+i];
            #pragma unroll
            for (int d = 0; d < 4; d++) rb[d] = vs[kk][tx*4+d];
            #pragma unroll
            for (int i = 0; i < 4; i++)
                #pragma unroll
                for (int d = 0; d < 4; d++) acc[i][d] += ra[i] * rb[d];
        }
        __syncthreads();
    }
    #pragma unroll
    for (int i = 0; i < 4; i++) {
        size_t orow = ((size_t)(b * NN + i0 + ty*4 + i)) * DDIM + h * 64;
        #pragma unroll
        for (int d = 0; d < 4; d++) O[orow + tx*4 + d] = acc[i][d];
    }
}

// ---------------- GEGLU: act = a * gelu_exact(g) ----------------
__global__ void __launch_bounds__(256) geglu_kernel(const float* __restrict__ h,
                                                    float* __restrict__ act)
{
    size_t idx = (size_t)blockIdx.x * blockDim.x + threadIdx.x;  // over TOK*FFHID/4
    size_t i  = idx / (FFHID / 4);
    size_t c4 = idx % (FFHID / 4);
    float4 a = *(const float4*)(h + i * FFIN + c4 * 4);
    float4 g = *(const float4*)(h + i * FFIN + FFHID + c4 * 4);
    const float kInvSqrt2 = 0.70710678118654752f;
    float4 o;
    o.x = a.x * (0.5f * g.x * (1.f + erff(g.x * kInvSqrt2)));
    o.y = a.y * (0.5f * g.y * (1.f + erff(g.y * kInvSqrt2)));
    o.z = a.z * (0.5f * g.z * (1.f + erff(g.z * kInvSqrt2)));
    o.w = a.w * (0.5f * g.w * (1.f + erff(g.w * kInvSqrt2)));
    *(float4*)(act + i * FFHID + c4 * 4) = o;
}

// ---------------- launch ----------------
extern "C" void kernel_launch(void* const* d_in, const int* in_sizes, int n_in,
                              void* d_out, int out_size)
{
    const float* x    = (const float*)d_in[0];
    const float* ctx  = (const float*)d_in[1];
    const float* n1w  = (const float*)d_in[2];
    const float* n1b  = (const float*)d_in[3];
    const float* n2w  = (const float*)d_in[4];
    const float* n2b  = (const float*)d_in[5];
    const float* n3w  = (const float*)d_in[6];
    const float* n3b  = (const float*)d_in[7];
    const float* a1wq = (const float*)d_in[8];
    const float* a1wk = (const float*)d_in[9];
    const float* a1wv = (const float*)d_in[10];
    const float* a1wo = (const float*)d_in[11];
    const float* a1bo = (const float*)d_in[12];
    const float* a2wq = (const float*)d_in[13];
    const float* a2wk = (const float*)d_in[14];
    const float* a2wv = (const float*)d_in[15];
    const float* a2wo = (const float*)d_in[16];
    const float* a2bo = (const float*)d_in[17];
    const float* ffw1 = (const float*)d_in[18];
    const float* ffb1 = (const float*)d_in[19];
    const float* ffw2 = (const float*)d_in[20];
    const float* ffb2 = (const float*)d_in[21];
    const float* d1q  = (const float*)d_in[22];
    const float* d1k  = (const float*)d_in[23];
    const float* d1v  = (const float*)d_in[24];
    const float* d1w  = (const float*)d_in[25];
    const float* d2q  = (const float*)d_in[26];
    const float* d2k  = (const float*)d_in[27];
    const float* d2v  = (const float*)d_in[28];
    const float* d2w  = (const float*)d_in[29];
    float* out = (float*)d_out;

    float *ln, *q, *k, *v, *ao, *sim;
    cudaGetSymbolAddress((void**)&ln,  g_ln);
    cudaGetSymbolAddress((void**)&q,   g_q);
    cudaGetSymbolAddress((void**)&k,   g_k);
    cudaGetSymbolAddress((void**)&v,   g_v);
    cudaGetSymbolAddress((void**)&ao,  g_ao);
    cudaGetSymbolAddress((void**)&sim, g_sim);
    float* hbuf = sim;                           // FF hidden reuses sim buffer
    float* act  = sim + (size_t)TOK * FFIN;      // FF act after hidden

    // ---- attn1 (self) ----
    ln_kernel<<<TOK, 256>>>(x, n1w, n1b, ln);
    sgemm_k<0><<<dim3(8, 32), 256>>>(ln, a1wq, nullptr, nullptr, q, TOK, DDIM, DDIM, d1q);
    sgemm_k<0><<<dim3(8, 32), 256>>>(ln, a1wk, nullptr, nullptr, k, TOK, DDIM, DDIM, d1k);
    sgemm_k<0><<<dim3(8, 32), 256>>>(ln, a1wv, nullptr, nullptr, v, TOK, DDIM, DDIM, d1v);
    sim_kernel<<<dim3(16, 16, BB*HH), 256>>>(q, k, sim, NN);
    softmax_quant<<<BB*HH*NN, 128>>>(sim, NN, d1w);
    av_kernel<<<dim3(16, BB*HH), 256>>>(sim, v, ao, NN);
    sgemm_k<1><<<dim3(8, 32), 256>>>(ao, a1wo, a1bo, x, out, TOK, DDIM, DDIM, nullptr);

    // ---- attn2 (cross) ----
    ln_kernel<<<TOK, 256>>>(out, n2w, n2b, ln);
    sgemm_k<0><<<dim3(8, 32), 256>>>(ln,  a2wq, nullptr, nullptr, q, TOK,  DDIM, DDIM, d2q);
    sgemm_k<0><<<dim3(8, 3),  256>>>(ctx, a2wk, nullptr, nullptr, k, CTOK, DDIM, CTXD, d2k);
    sgemm_k<0><<<dim3(8, 3),  256>>>(ctx, a2wv, nullptr, nullptr, v, CTOK, DDIM, CTXD, d2v);
    sim_kernel<<<dim3(2, 16, BB*HH), 256>>>(q, k, sim, CTXN);
    softmax_quant<<<BB*HH*NN, 128>>>(sim, CTXN, d2w);
    av_kernel<<<dim3(16, BB*HH), 256>>>(sim, v, ao, CTXN);
    sgemm_k<1><<<dim3(8, 32), 256>>>(ao, a2wo, a2bo, out, out, TOK, DDIM, DDIM, nullptr);

    // ---- GEGLU FF ----
    ln_kernel<<<TOK, 256>>>(out, n3w, n3b, ln);
    sgemm_k<2><<<dim3(64, 32), 256>>>(ln, ffw1, ffb1, nullptr, hbuf, TOK, FFIN, DDIM, nullptr);
    geglu_kernel<<<(TOK * (FFHID/4)) / 256, 256>>>(hbuf, act);
    sgemm_k<1><<<dim3(8, 32), 256>>>(act, ffw2, ffb2, out, out, TOK, DDIM, FFHID, nullptr);
}

// round 2
// speedup vs baseline: 1.3212x; 1.3212x over previous
#include <cuda_runtime.h>
#include <math.h>

// ---------------- problem constants ----------------
#define BB 4
#define NN 1024
#define DDIM 1024
#define HH 16
#define CTXN 77
#define CTXD 768
#define FFIN 8192
#define FFHID 4096
#define TOK (BB*NN)      // 4096
#define CTOK (BB*CTXN)   // 308
#define SCALE 0.125f     // 64^-0.5

// ---------------- scratch (device globals) ----------------
__device__ float g_ln[(size_t)TOK*DDIM];
__device__ float g_ao[(size_t)TOK*DDIM];
__device__ char  g_q8[(size_t)TOK*DDIM];           // [b,h,n,64] int8 codes
__device__ char  g_k8[(size_t)TOK*DDIM];
__device__ char  g_v8[(size_t)TOK*DDIM];
__device__ unsigned char g_w8[(size_t)BB*HH*NN*NN]; // softmax weight codes (padded rows)
__device__ float g_sim[(size_t)BB*HH*NN*NN];        // scores; reused for FF hidden + act

// ---------------- LayerNorm ----------------
__global__ void __launch_bounds__(256) ln_kernel(const float* __restrict__ x,
    const float* __restrict__ w, const float* __restrict__ b, float* __restrict__ out)
{
    int row = blockIdx.x;
    int t = threadIdx.x;
    const float4* xr = (const float4*)(x + (size_t)row * DDIM);
    float4 v = xr[t];
    float s  = v.x + v.y + v.z + v.w;
    float ss = v.x*v.x + v.y*v.y + v.z*v.z + v.w*v.w;
    #pragma unroll
    for (int o = 16; o; o >>= 1) {
        s  += __shfl_xor_sync(0xffffffffu, s, o);
        ss += __shfl_xor_sync(0xffffffffu, ss, o);
    }
    __shared__ float sh_s[8], sh_q[8];
    int wid = t >> 5, lane = t & 31;
    if (lane == 0) { sh_s[wid] = s; sh_q[wid] = ss; }
    __syncthreads();
    if (t == 0) {
        float a = 0.f, c = 0.f;
        #pragma unroll
        for (int i = 0; i < 8; i++) { a += sh_s[i]; c += sh_q[i]; }
        float m = a * (1.0f/DDIM);
        float var = c * (1.0f/DDIM) - m*m;
        sh_s[0] = m;
        sh_q[0] = rsqrtf(var + 1e-5f);
    }
    __syncthreads();
    float m = sh_s[0], r = sh_q[0];
    float4 wv = ((const float4*)w)[t];
    float4 bv = ((const float4*)b)[t];
    float4 o4;
    o4.x = (v.x - m) * r * wv.x + bv.x;
    o4.y = (v.y - m) * r * wv.y + bv.y;
    o4.z = (v.z - m) * r * wv.z + bv.z;
    o4.w = (v.w - m) * r * wv.w + bv.w;
    ((float4*)(out + (size_t)row * DDIM))[t] = o4;
}

// ---------------- pipelined SGEMM 128x128x16, 256 threads, 8x8/thread -------
// MODE 0: fake-quant -> int8 codes into head-major layout [b,h,n,64]
// MODE 1: + bias[n] + res -> fp32
// MODE 2: + bias[n]       -> fp32
template<int MODE, bool BOUNDS>
__global__ void __launch_bounds__(256) sgemm_k(
    const float* __restrict__ A, const float* __restrict__ W,
    const float* __restrict__ bias, const float* __restrict__ res,
    float* __restrict__ C, char* __restrict__ Cq,
    int M, int N, int K, const float* __restrict__ dptr, int rows_per_b)
{
    __shared__ float As[2][16][132];   // [buf][k][m]
    __shared__ float Bs[2][16][128];   // [buf][k][n]
    const int tid  = threadIdx.x;
    const int crow = blockIdx.y * 128;
    const int ccol = blockIdx.x * 128;

    const int ar = tid >> 2;          // 0..63
    const int ac = (tid & 3) * 4;     // 0,4,8,12
    const int bk = tid >> 5;          // 0..7
    const int bn = (tid & 31) * 4;    // 0..124

    const int tr = (tid >> 4) * 8;
    const int tc = (tid & 15) * 8;

    float acc[8][8];
    #pragma unroll
    for (int i = 0; i < 8; i++)
        #pragma unroll
        for (int j = 0; j < 8; j++) acc[i][j] = 0.f;

    float4 pa0, pa1, pb0, pb1;

    auto gload = [&](int k0) {
        if (BOUNDS) {
            pa0 = (crow+ar    < M) ? *(const float4*)(A + (size_t)(crow+ar   )*K + k0 + ac)
                                   : make_float4(0.f,0.f,0.f,0.f);
            pa1 = (crow+ar+64 < M) ? *(const float4*)(A + (size_t)(crow+ar+64)*K + k0 + ac)
                                   : make_float4(0.f,0.f,0.f,0.f);
        } else {
            pa0 = *(const float4*)(A + (size_t)(crow+ar   )*K + k0 + ac);
            pa1 = *(const float4*)(A + (size_t)(crow+ar+64)*K + k0 + ac);
        }
        pb0 = *(const float4*)(W + (size_t)(k0+bk  )*N + ccol + bn);
        pb1 = *(const float4*)(W + (size_t)(k0+bk+8)*N + ccol + bn);
    };
    auto sstore = [&](int buf) {
        As[buf][ac+0][ar] = pa0.x; As[buf][ac+1][ar] = pa0.y;
        As[buf][ac+2][ar] = pa0.z; As[buf][ac+3][ar] = pa0.w;
        As[buf][ac+0][ar+64] = pa1.x; As[buf][ac+1][ar+64] = pa1.y;
        As[buf][ac+2][ar+64] = pa1.z; As[buf][ac+3][ar+64] = pa1.w;
        *(float4*)&Bs[buf][bk  ][bn] = pb0;
        *(float4*)&Bs[buf][bk+8][bn] = pb1;
    };
    auto compute = [&](int buf) {
        #pragma unroll
        for (int kk = 0; kk < 16; kk++) {
            float4 a0 = *(const float4*)&As[buf][kk][tr];
            float4 a1 = *(const float4*)&As[buf][kk][tr+4];
            float4 b0 = *(const float4*)&Bs[buf][kk][tc];
            float4 b1 = *(const float4*)&Bs[buf][kk][tc+4];
            float ra[8] = {a0.x,a0.y,a0.z,a0.w,a1.x,a1.y,a1.z,a1.w};
            float rb[8] = {b0.x,b0.y,b0.z,b0.w,b1.x,b1.y,b1.z,b1.w};
            #pragma unroll
            for (int i = 0; i < 8; i++)
                #pragma unroll
                for (int j = 0; j < 8; j++) acc[i][j] += ra[i] * rb[j];
        }
    };

    gload(0); sstore(0); __syncthreads();
    const int T = K >> 4;
    for (int t = 1; t < T; t++) {
        gload(t << 4);
        compute((t-1) & 1);
        sstore(t & 1);
        __syncthreads();
    }
    compute((T-1) & 1);

    if (MODE == 0) {
        float d = *dptr;
        float invd = 1.0f / d;
        int h  = (ccol + tc) >> 6;      // head (tc..tc+7 same head)
        int dd = (ccol + tc) & 63;
        #pragma unroll
        for (int i = 0; i < 8; i++) {
            int r = crow + tr + i;
            if (BOUNDS && r >= M) continue;
            int b = r / rows_per_b;
            int n = r - b * rows_per_b;
            size_t base = ((size_t)(b*HH + h)*rows_per_b + n)*64 + dd;
            char q[8];
            #pragma unroll
            for (int j = 0; j < 8; j++) {
                float s = fminf(fmaxf(rintf(acc[i][j] * invd), -128.f), 127.f);
                q[j] = (char)(int)s;
            }
            *(char4*)(Cq + base)     = make_char4(q[0],q[1],q[2],q[3]);
            *(char4*)(Cq + base + 4) = make_char4(q[4],q[5],q[6],q[7]);
        }
    } else {
        float4 bv0 = *(const float4*)(bias + ccol + tc);
        float4 bv1 = *(const float4*)(bias + ccol + tc + 4);
        #pragma unroll
        for (int i = 0; i < 8; i++) {
            int r = crow + tr + i;
            if (BOUNDS && r >= M) continue;
            size_t off = (size_t)r * N + ccol + tc;
            float4 o0, o1;
            o0.x = acc[i][0] + bv0.x; o0.y = acc[i][1] + bv0.y;
            o0.z = acc[i][2] + bv0.z; o0.w = acc[i][3] + bv0.w;
            o1.x = acc[i][4] + bv1.x; o1.y = acc[i][5] + bv1.y;
            o1.z = acc[i][6] + bv1.z; o1.w = acc[i][7] + bv1.w;
            if (MODE == 1) {
                float4 r0 = *(const float4*)(res + off);
                float4 r1 = *(const float4*)(res + off + 4);
                o0.x += r0.x; o0.y += r0.y; o0.z += r0.z; o0.w += r0.w;
                o1.x += r1.x; o1.y += r1.y; o1.z += r1.z; o1.w += r1.w;
            }
            *(float4*)(C + off)     = o0;
            *(float4*)(C + off + 4) = o1;
        }
    }
}

// ---------------- int8 scores: S = (dq*dk*SCALE) * (q8 . k8) ----------------
__global__ void __launch_bounds__(256) sim8_kernel(
    const char* __restrict__ Q8, const char* __restrict__ K8,
    float* __restrict__ S, int nk,
    const float* __restrict__ dq, const float* __restrict__ dk)
{
    int bh = blockIdx.z;
    int i0 = blockIdx.y * 64;
    int j0 = blockIdx.x * 64;
    __shared__ int qs[16][68];   // [k-pack][i-row]
    __shared__ int ks[16][68];   // [k-pack][j-row]
    int tid = threadIdx.x;
    int row = tid >> 2;
    int c4  = (tid & 3) * 4;     // pack base
    {
        int4 qv = *(const int4*)(Q8 + ((size_t)bh*NN + i0 + row)*64 + c4*4);
        qs[c4+0][row]=qv.x; qs[c4+1][row]=qv.y; qs[c4+2][row]=qv.z; qs[c4+3][row]=qv.w;
        int jr = j0 + row;
        int4 kv = make_int4(0,0,0,0);
        if (jr < nk) kv = *(const int4*)(K8 + ((size_t)bh*nk + jr)*64 + c4*4);
        ks[c4+0][row]=kv.x; ks[c4+1][row]=kv.y; ks[c4+2][row]=kv.z; ks[c4+3][row]=kv.w;
    }
    __syncthreads();
    int ty = tid >> 4, tx = tid & 15;
    int acc[4][4];
    #pragma unroll
    for (int i = 0; i < 4; i++)
        #pragma unroll
        for (int j = 0; j < 4; j++) acc[i][j] = 0;
    #pragma unroll
    for (int kk = 0; kk < 16; kk++) {
        int a[4], b[4];
        *(int4*)a = *(const int4*)&qs[kk][ty*4];
        *(int4*)b = *(const int4*)&ks[kk][tx*4];
        #pragma unroll
        for (int i = 0; i < 4; i++)
            #pragma unroll
            for (int j = 0; j < 4; j++) acc[i][j] = __dp4a(a[i], b[j], acc[i][j]);
    }
    float sc = dq[0] * dk[0] * SCALE;
    #pragma unroll
    for (int i = 0; i < 4; i++) {
        size_t ro = ((size_t)bh*NN + i0 + ty*4 + i) * nk;
        #pragma unroll
        for (int j = 0; j < 4; j++) {
            int jj = j0 + tx*4 + j;
            if (jj < nk) S[ro + jj] = (float)acc[i][j] * sc;
        }
    }
}

// ---------------- softmax + weight quant -> u8 codes (zp=0), padded rows ----
__global__ void __launch_bounds__(128) softmax_quant(
    const float* __restrict__ S, unsigned char* __restrict__ W8,
    int cols, int colsp, const float* __restrict__ dptr)
{
    size_t row = blockIdx.x;
    const float* p = S + row * (size_t)cols;
    unsigned char* o = W8 + row * (size_t)colsp;
    int t = threadIdx.x;
    float buf[8];
    int nb = 0;
    float m = -INFINITY;
    for (int c = t; c < cols; c += 128) {
        float v = p[c];
        buf[nb++] = v;
        m = fmaxf(m, v);
    }
    #pragma unroll
    for (int off = 16; off; off >>= 1) m = fmaxf(m, __shfl_xor_sync(0xffffffffu, m, off));
    __shared__ float redm[4], reds[4];
    if ((t & 31) == 0) redm[t >> 5] = m;
    __syncthreads();
    m = fmaxf(fmaxf(redm[0], redm[1]), fmaxf(redm[2], redm[3]));
    float sum = 0.f;
    for (int i = 0; i < nb; i++) { buf[i] = expf(buf[i] - m); sum += buf[i]; }
    #pragma unroll
    for (int off = 16; off; off >>= 1) sum += __shfl_xor_sync(0xffffffffu, sum, off);
    if ((t & 31) == 0) reds[t >> 5] = sum;
    __syncthreads();
    sum = reds[0] + reds[1] + reds[2] + reds[3];
    float inv = 1.0f / sum;
    float invd = 1.0f / dptr[0];
    nb = 0;
    for (int c = t; c < colsp; c += 128) {
        unsigned char ob = 0;
        if (c < cols) {
            float q = rintf(buf[nb++] * inv * invd);
            ob = (unsigned char)(int)fminf(fmaxf(q, 0.f), 255.f);
        }
        o[c] = ob;
    }
}

// ---------------- AV: O = (dw*dv) * (w8 . v8), u8 x s8 dp4a ----------------
__global__ void __launch_bounds__(256) av8_kernel(
    const unsigned char* __restrict__ W8, const char* __restrict__ V8,
    float* __restrict__ O, int nk, int colsp,
    const float* __restrict__ dw, const float* __restrict__ dv)
{
    int bh = blockIdx.y; int b = bh >> 4; int h = bh & 15;
    int i0 = blockIdx.x * 64;
    __shared__ int ws[64][20];               // [i-row][j-pack]
    __shared__ unsigned char vtb[64][76];    // [d-row][j-byte]
    int tid = threadIdx.x;
    int row = tid >> 2;
    int c16 = (tid & 3) * 16;
    int ty = tid >> 4, tx = tid & 15;
    int acc[4][4];
    #pragma unroll
    for (int i = 0; i < 4; i++)
        #pragma unroll
        for (int d = 0; d < 4; d++) acc[i][d] = 0;

    const unsigned char* wb = W8 + ((size_t)bh*NN + i0 + row) * colsp + c16;
    const char* vb = V8 + ((size_t)bh*nk)*64;

    for (int j0 = 0; j0 < nk; j0 += 64) {
        uint4 wv = *(const uint4*)(wb + j0);
        *(uint4*)&ws[row][(tid & 3) * 4] = wv;
        int jr = j0 + row;
        int4 vv = make_int4(0,0,0,0);
        if (jr < nk) vv = *(const int4*)(vb + (size_t)jr*64 + c16);
        union { int4 v; unsigned char bb[16]; } u; u.v = vv;
        #pragma unroll
        for (int i = 0; i < 16; i++) vtb[c16 + i][row] = u.bb[i];
        __syncthreads();
        #pragma unroll
        for (int kk = 0; kk < 16; kk++) {
            int a[4], bb[4];
            #pragma unroll
            for (int i = 0; i < 4; i++) a[i] = ws[ty*4 + i][kk];
            #pragma unroll
            for (int d = 0; d < 4; d++) bb[d] = *(const int*)&vtb[tx*4 + d][kk*4];
            #pragma unroll
            for (int i = 0; i < 4; i++)
                #pragma unroll
                for (int d = 0; d < 4; d++)
                    asm("dp4a.u32.s32 %0, %1, %2, %3;"
                        : "=r"(acc[i][d]) : "r"(a[i]), "r"(bb[d]), "r"(acc[i][d]));
        }
        __syncthreads();
    }
    float sc = dw[0] * dv[0];
    #pragma unroll
    for (int i = 0; i < 4; i++) {
        size_t ro = ((size_t)(b*NN + i0 + ty*4 + i)) * DDIM + h*64 + tx*4;
        float4 f;
        f.x = (float)acc[i][0] * sc;
        f.y = (float)acc[i][1] * sc;
        f.z = (float)acc[i][2] * sc;
        f.w = (float)acc[i][3] * sc;
        *(float4*)&O[ro] = f;
    }
}

// ---------------- GEGLU ----------------
__global__ void __launch_bounds__(256) geglu_kernel(const float* __restrict__ h,
                                                    float* __restrict__ act)
{
    size_t idx = (size_t)blockIdx.x * blockDim.x + threadIdx.x;
    size_t i  = idx / (FFHID / 4);
    size_t c4 = idx % (FFHID / 4);
    float4 a = *(const float4*)(h + i * FFIN + c4 * 4);
    float4 g = *(const float4*)(h + i * FFIN + FFHID + c4 * 4);
    const float kInvSqrt2 = 0.70710678118654752f;
    float4 o;
    o.x = a.x * (0.5f * g.x * (1.f + erff(g.x * kInvSqrt2)));
    o.y = a.y * (0.5f * g.y * (1.f + erff(g.y * kInvSqrt2)));
    o.z = a.z * (0.5f * g.z * (1.f + erff(g.z * kInvSqrt2)));
    o.w = a.w * (0.5f * g.w * (1.f + erff(g.w * kInvSqrt2)));
    *(float4*)(act + i * FFHID + c4 * 4) = o;
}

// ---------------- launch ----------------
extern "C" void kernel_launch(void* const* d_in, const int* in_sizes, int n_in,
                              void* d_out, int out_size)
{
    const float* x    = (const float*)d_in[0];
    const float* ctx  = (const float*)d_in[1];
    const float* n1w  = (const float*)d_in[2];
    const float* n1b  = (const float*)d_in[3];
    const float* n2w  = (const float*)d_in[4];
    const float* n2b  = (const float*)d_in[5];
    const float* n3w  = (const float*)d_in[6];
    const float* n3b  = (const float*)d_in[7];
    const float* a1wq = (const float*)d_in[8];
    const float* a1wk = (const float*)d_in[9];
    const float* a1wv = (const float*)d_in[10];
    const float* a1wo = (const float*)d_in[11];
    const float* a1bo = (const float*)d_in[12];
    const float* a2wq = (const float*)d_in[13];
    const float* a2wk = (const float*)d_in[14];
    const float* a2wv = (const float*)d_in[15];
    const float* a2wo = (const float*)d_in[16];
    const float* a2bo = (const float*)d_in[17];
    const float* ffw1 = (const float*)d_in[18];
    const float* ffb1 = (const float*)d_in[19];
    const float* ffw2 = (const float*)d_in[20];
    const float* ffb2 = (const float*)d_in[21];
    const float* d1q  = (const float*)d_in[22];
    const float* d1k  = (const float*)d_in[23];
    const float* d1v  = (const float*)d_in[24];
    const float* d1w  = (const float*)d_in[25];
    const float* d2q  = (const float*)d_in[26];
    const float* d2k  = (const float*)d_in[27];
    const float* d2v  = (const float*)d_in[28];
    const float* d2w  = (const float*)d_in[29];
    float* out = (float*)d_out;

    float *ln, *ao, *sim;
    char *q8, *k8, *v8;
    unsigned char *w8;
    cudaGetSymbolAddress((void**)&ln,  g_ln);
    cudaGetSymbolAddress((void**)&ao,  g_ao);
    cudaGetSymbolAddress((void**)&sim, g_sim);
    cudaGetSymbolAddress((void**)&q8,  g_q8);
    cudaGetSymbolAddress((void**)&k8,  g_k8);
    cudaGetSymbolAddress((void**)&v8,  g_v8);
    cudaGetSymbolAddress((void**)&w8,  g_w8);
    float* hbuf = sim;                        // FF hidden reuses sim buffer
    float* act  = sim + (size_t)TOK * FFIN;   // FF act after hidden

    // ---- attn1 (self) ----
    ln_kernel<<<TOK, 256>>>(x, n1w, n1b, ln);
    sgemm_k<0,false><<<dim3(8,32), 256>>>(ln, a1wq, nullptr, nullptr, nullptr, q8, TOK, DDIM, DDIM, d1q, NN);
    sgemm_k<0,false><<<dim3(8,32), 256>>>(ln, a1wk, nullptr, nullptr, nullptr, k8, TOK, DDIM, DDIM, d1k, NN);
    sgemm_k<0,false><<<dim3(8,32), 256>>>(ln, a1wv, nullptr, nullptr, nullptr, v8, TOK, DDIM, DDIM, d1v, NN);
    sim8_kernel<<<dim3(16,16,BB*HH), 256>>>(q8, k8, sim, NN, d1q, d1k);
    softmax_quant<<<BB*HH*NN, 128>>>(sim, w8, NN, NN, d1w);
    av8_kernel<<<dim3(16,BB*HH), 256>>>(w8, v8, ao, NN, NN, d1w, d1v);
    sgemm_k<1,false><<<dim3(8,32), 256>>>(ao, a1wo, a1bo, x, out, nullptr, TOK, DDIM, DDIM, nullptr, 0);

    // ---- attn2 (cross) ----
    ln_kernel<<<TOK, 256>>>(out, n2w, n2b, ln);
    sgemm_k<0,false><<<dim3(8,32), 256>>>(ln,  a2wq, nullptr, nullptr, nullptr, q8, TOK,  DDIM, DDIM, d2q, NN);
    sgemm_k<0,true ><<<dim3(8,3),  256>>>(ctx, a2wk, nullptr, nullptr, nullptr, k8, CTOK, DDIM, CTXD, d2k, CTXN);
    sgemm_k<0,true ><<<dim3(8,3),  256>>>(ctx, a2wv, nullptr, nullptr, nullptr, v8, CTOK, DDIM, CTXD, d2v, CTXN);
    sim8_kernel<<<dim3(2,16,BB*HH), 256>>>(q8, k8, sim, CTXN, d2q, d2k);
    softmax_quant<<<BB*HH*NN, 128>>>(sim, w8, CTXN, 128, d2w);
    av8_kernel<<<dim3(16,BB*HH), 256>>>(w8, v8, ao, CTXN, 128, d2w, d2v);
    sgemm_k<1,false><<<dim3(8,32), 256>>>(ao, a2wo, a2bo, out, out, nullptr, TOK, DDIM, DDIM, nullptr, 0);

    // ---- GEGLU FF ----
    ln_kernel<<<TOK, 256>>>(out, n3w, n3b, ln);
    sgemm_k<2,false><<<dim3(64,32), 256>>>(ln, ffw1, ffb1, nullptr, hbuf, nullptr, TOK, FFIN, DDIM, nullptr, 0);
    geglu_kernel<<<(TOK*(FFHID/4))/256, 256>>>(hbuf, act);
    sgemm_k<1,false><<<dim3(8,32), 256>>>(act, ffw2, ffb2, out, out, nullptr, TOK, DDIM, FFHID, nullptr, 0);
}

// round 7
// speedup vs baseline: 1.4630x; 1.1073x over previous
#include <cuda_runtime.h>
#include <cuda_fp16.h>
#include <math.h>
#include <stdint.h>

// ---------------- problem constants ----------------
#define BB 4
#define NN 1024
#define DDIM 1024
#define HH 16
#define CTXN 77
#define CTXD 768
#define FFIN 8192
#define FFHID 4096
#define TOK (BB*NN)      // 4096
#define CTOK (BB*CTXN)   // 308
#define SCALE 0.125f
#define RSC 2048.0f      // residual plane scale (2^11)
#define RSCINV (1.0f/2048.0f)

// ---------------- scratch (device globals) ----------------
__device__ char  g_q8[(size_t)TOK*DDIM];
__device__ char  g_k8[(size_t)TOK*DDIM];
__device__ char  g_v8[(size_t)TOK*DDIM];
__device__ unsigned char g_w8[(size_t)BB*HH*NN*NN];
__device__ float g_sim[(size_t)BB*HH*NN*NN];   // scores; reused for FF hidden

// activation half-split planes (max 4096x4096)
#define AMAX ((size_t)TOK*FFHID)
__device__ __half g_ah[AMAX];
__device__ __half g_am[AMAX];

// weight split planes, concatenated [N,K] layouts
#define OFF_WQ1  ((size_t)0)
#define OFF_WK1  ((size_t)1048576)
#define OFF_WV1  ((size_t)2097152)
#define OFF_WO1  ((size_t)3145728)
#define OFF_WQ2  ((size_t)4194304)
#define OFF_WO2  ((size_t)5242880)
#define OFF_WK2  ((size_t)6291456)
#define OFF_WV2  ((size_t)(6291456+786432))
#define OFF_FF1  ((size_t)(6291456+1572864))
#define OFF_FF2  ((size_t)(OFF_FF1+8388608))
#define WTOT     ((size_t)(OFF_FF2+4194304))
__device__ __half g_wh[WTOT];
__device__ __half g_wm[WTOT];

// ---------------- helpers ----------------
__device__ __forceinline__ uint32_t smem_u32(const void* p) {
    uint32_t a;
    asm("{ .reg .u64 t; cvta.to.shared.u64 t, %1; cvt.u32.u64 %0, t; }" : "=r"(a) : "l"(p));
    return a;
}
__device__ __forceinline__ void cpasync16(uint32_t s, const void* g, int sz) {
    asm volatile("cp.async.cg.shared.global [%0], [%1], 16, %2;"
                 :: "r"(s), "l"(g), "r"(sz));
}
__device__ __forceinline__ void cpcommit() { asm volatile("cp.async.commit_group;"); }
__device__ __forceinline__ void cpwait2()  { asm volatile("cp.async.wait_group 2;"); }

// scaled split: x ~= h + m/2048, with m in fp16 normal range
__device__ __forceinline__ void split2(float x, __half& h, __half& m) {
    h = __float2half_rn(x);
    m = __float2half_rn((x - __half2float(h)) * RSC);
}

// ---------------- LayerNorm -> (h,m) planes ----------------
__global__ void __launch_bounds__(256) ln_kernel(const float* __restrict__ x,
    const float* __restrict__ w, const float* __restrict__ b,
    __half* __restrict__ H, __half* __restrict__ Mp)
{
    int row = blockIdx.x;
    int t = threadIdx.x;
    const float4* xr = (const float4*)(x + (size_t)row * DDIM);
    float4 v = xr[t];
    float s  = v.x + v.y + v.z + v.w;
    float ss = v.x*v.x + v.y*v.y + v.z*v.z + v.w*v.w;
    #pragma unroll
    for (int o = 16; o; o >>= 1) {
        s  += __shfl_xor_sync(0xffffffffu, s, o);
        ss += __shfl_xor_sync(0xffffffffu, ss, o);
    }
    __shared__ float sh_s[8], sh_q[8];
    int wid = t >> 5, lane = t & 31;
    if (lane == 0) { sh_s[wid] = s; sh_q[wid] = ss; }
    __syncthreads();
    if (t == 0) {
        float a = 0.f, c = 0.f;
        #pragma unroll
        for (int i = 0; i < 8; i++) { a += sh_s[i]; c += sh_q[i]; }
        float m = a * (1.0f/DDIM);
        float var = c * (1.0f/DDIM) - m*m;
        sh_s[0] = m;
        sh_q[0] = rsqrtf(var + 1e-5f);
    }
    __syncthreads();
    float m = sh_s[0], r = sh_q[0];
    float4 wv = ((const float4*)w)[t];
    float4 bv = ((const float4*)b)[t];
    float o[4];
    o[0] = (v.x - m) * r * wv.x + bv.x;
    o[1] = (v.y - m) * r * wv.y + bv.y;
    o[2] = (v.z - m) * r * wv.z + bv.z;
    o[3] = (v.w - m) * r * wv.w + bv.w;
    ushort4 uh, um;
    __half h0, m0;
    split2(o[0], h0, m0); uh.x = __half_as_ushort(h0); um.x = __half_as_ushort(m0);
    split2(o[1], h0, m0); uh.y = __half_as_ushort(h0); um.y = __half_as_ushort(m0);
    split2(o[2], h0, m0); uh.z = __half_as_ushort(h0); um.z = __half_as_ushort(m0);
    split2(o[3], h0, m0); uh.w = __half_as_ushort(h0); um.w = __half_as_ushort(m0);
    ((ushort4*)(H  + (size_t)row * DDIM))[t] = uh;
    ((ushort4*)(Mp + (size_t)row * DDIM))[t] = um;
}

// ---------------- activation split (ctx only) ----------------
__global__ void __launch_bounds__(256) asplit_k(const float* __restrict__ A,
    __half* __restrict__ H, __half* __restrict__ Mp, int n4)
{
    int i = blockIdx.x * 256 + threadIdx.x;
    if (i >= n4) return;
    float4 v = ((const float4*)A)[i];
    ushort4 uh, um;
    __half h0, m0;
    split2(v.x, h0, m0); uh.x = __half_as_ushort(h0); um.x = __half_as_ushort(m0);
    split2(v.y, h0, m0); uh.y = __half_as_ushort(h0); um.y = __half_as_ushort(m0);
    split2(v.z, h0, m0); uh.z = __half_as_ushort(h0); um.z = __half_as_ushort(m0);
    split2(v.w, h0, m0); uh.w = __half_as_ushort(h0); um.w = __half_as_ushort(m0);
    ((ushort4*)H)[i] = uh; ((ushort4*)Mp)[i] = um;
}

// ---------------- weight transpose+split: W[K,N] -> [N,K] half x2 ----------
__global__ void __launch_bounds__(256) wsplit_k(const float* __restrict__ W,
    __half* __restrict__ H, __half* __restrict__ Mp, int K, int N)
{
    __shared__ float tile[32][33];
    int n0 = blockIdx.x * 32, k0 = blockIdx.y * 32;
    int tx = threadIdx.x & 31, ty = threadIdx.x >> 5;
    #pragma unroll
    for (int i = 0; i < 4; i++)
        tile[ty + i*8][tx] = W[(size_t)(k0 + ty + i*8) * N + n0 + tx];
    __syncthreads();
    #pragma unroll
    for (int i = 0; i < 4; i++) {
        int nl = ty + i*8;
        float x = tile[tx][nl];
        __half h, m;
        split2(x, h, m);
        size_t o = (size_t)(n0 + nl) * K + k0 + tx;
        H[o] = h; Mp[o] = m;
    }
}

// ---------------- HMMA GEMM: D[M,N] = A[M,K] @ T[N,K]^T, fp16 split --------
// Dual accumulators: mma tile-acc flushed into fp32 master (RN FADD) every 2
// iterations to break tensor-core RZ accumulation bias (64-add chains -> 4).
// TERMS=4 (MODE 0): (m,m) -> x1/2048 -> (h,m),(m,h) -> x1/2048 -> (h,h)
// TERMS=3 (MODE 1/2): (h,m),(m,h) -> x1/2048 -> (h,h)
#define BM 128
#define BN 128
#define BK 32
#define ROWB 80
#define ATILE (BM*ROWB)
#define STAGEB (2*ATILE)
#define NSTAGE 3
#define GSMEM (NSTAGE*STAGEB)

template<int MODE, bool BOUNDS, int TERMS>
__global__ void __launch_bounds__(256, 1) hgemm(
    const __half* __restrict__ Ah, const __half* __restrict__ Am,
    const __half* __restrict__ Bh, const __half* __restrict__ Bm,
    const float* __restrict__ bias, const float* __restrict__ res,
    float* __restrict__ Cf, char* __restrict__ Cq,
    int M, int N, int K, const float* __restrict__ dptr, int rows_per_b)
{
    extern __shared__ char smem[];
    const uint32_t sb = smem_u32(smem);
    const int tid  = threadIdx.x;
    const int wid  = tid >> 5;
    const int lane = tid & 31;
    const int m0 = blockIdx.y * BM;
    const int n0 = blockIdx.x * BN;
    const int wrow = (wid >> 2) * 64;
    const int wcol = (wid & 3) * 32;

    const int KT32 = K >> 5;
    const int T = TERMS * KT32;   // always even for our shapes

    // per-term plane selection
    const __half* APL[4];
    const __half* BPL[4];
    if (TERMS == 4) {
        APL[0]=Am; BPL[0]=Bm;
        APL[1]=Ah; BPL[1]=Bm;
        APL[2]=Am; BPL[2]=Bh;
        APL[3]=Ah; BPL[3]=Bh;
    } else {
        APL[0]=Ah; BPL[0]=Bm;
        APL[1]=Am; BPL[1]=Bh;
        APL[2]=Ah; BPL[2]=Bh;
        APL[3]=Ah; BPL[3]=Bh;
    }

    int lkt = 0, lterm = 0;
    const __half* lpa = APL[0];
    const __half* lpb = BPL[0];

    const int arow = tid >> 1;
    const int aco  = (tid & 1) * 32;
    int grow = m0 + arow;
    if (BOUNDS && grow >= M) grow = M - 1;
    const int asz = (!BOUNDS || (m0 + arow) < M) ? 16 : 0;

    auto issue = [&](int buf) {
        const char* ga = (const char*)lpa + (((size_t)grow*K + lkt*BK) << 1) + aco;
        uint32_t sa = sb + buf*STAGEB + arow*ROWB + aco;
        cpasync16(sa,      ga,      asz);
        cpasync16(sa + 16, ga + 16, asz);
        const char* gb = (const char*)lpb + (((size_t)(n0+arow)*K + lkt*BK) << 1) + aco;
        uint32_t sbb = sb + buf*STAGEB + ATILE + arow*ROWB + aco;
        cpasync16(sbb,      gb,      16);
        cpasync16(sbb + 16, gb + 16, 16);
    };
    auto adv = [&]() {
        if (++lkt == KT32) {
            lkt = 0;
            ++lterm;
            lpa = APL[lterm < TERMS ? lterm : TERMS-1];
            lpb = BPL[lterm < TERMS ? lterm : TERMS-1];
        }
    };

    float acc[4][4][4];    // mma tile accumulator (short RZ chains)
    float accm[4][4][4];   // fp32 master accumulator (RN adds)
    #pragma unroll
    for (int i = 0; i < 4; i++)
        #pragma unroll
        for (int j = 0; j < 4; j++)
            #pragma unroll
            for (int r = 0; r < 4; r++) { acc[i][j][r] = 0.f; accm[i][j][r] = 0.f; }

    issue(0); adv(); cpcommit();
    issue(1); adv(); cpcommit();

    for (int it = 0; it < T; it++) {
        if (it + 2 < T) { issue((it + 2) % NSTAGE); adv(); }
        cpcommit();
        cpwait2();
        __syncthreads();
        // rescale points are even `it`; tile acc is zero there (flushed at odd it)
        bool resc = (TERMS == 4) ? (it == KT32 || it == 3*KT32) : (it == 2*KT32);
        if (resc) {
            #pragma unroll
            for (int i = 0; i < 4; i++)
                #pragma unroll
                for (int j = 0; j < 4; j++)
                    #pragma unroll
                    for (int r = 0; r < 4; r++) accm[i][j][r] *= RSCINV;
        }
        const uint32_t abase = sb + (it % NSTAGE) * STAGEB;
        const uint32_t bbase = abase + ATILE;
        #pragma unroll
        for (int kh = 0; kh < 2; kh++) {
            uint32_t b0[4], b1[4];
            #pragma unroll
            for (int nt = 0; nt < 4; nt++) {
                uint32_t ad = bbase + (wcol + nt*8 + (lane & 7))*ROWB
                            + kh*32 + ((lane >> 3) & 1)*16;
                asm volatile("ldmatrix.sync.aligned.m8n8.x2.shared.b16 {%0,%1}, [%2];"
                             : "=r"(b0[nt]), "=r"(b1[nt]) : "r"(ad));
            }
            #pragma unroll
            for (int mt = 0; mt < 4; mt++) {
                uint32_t a0, a1, a2, a3;
                uint32_t ad = abase + (wrow + mt*16 + ((lane >> 3) & 1)*8 + (lane & 7))*ROWB
                            + kh*32 + ((lane >> 4) & 1)*16;
                asm volatile("ldmatrix.sync.aligned.m8n8.x4.shared.b16 {%0,%1,%2,%3}, [%4];"
                             : "=r"(a0), "=r"(a1), "=r"(a2), "=r"(a3) : "r"(ad));
                #pragma unroll
                for (int nt = 0; nt < 4; nt++) {
                    asm volatile(
                        "mma.sync.aligned.m16n8k16.row.col.f32.f16.f16.f32 "
                        "{%0,%1,%2,%3}, {%4,%5,%6,%7}, {%8,%9}, {%0,%1,%2,%3};"
                        : "+f"(acc[mt][nt][0]), "+f"(acc[mt][nt][1]),
                          "+f"(acc[mt][nt][2]), "+f"(acc[mt][nt][3])
                        : "r"(a0), "r"(a1), "r"(a2), "r"(a3), "r"(b0[nt]), "r"(b1[nt]));
                }
            }
        }
        if (it & 1) {
            // flush tile acc into master with RN adds; restart RZ chain
            #pragma unroll
            for (int i = 0; i < 4; i++)
                #pragma unroll
                for (int j = 0; j < 4; j++)
                    #pragma unroll
                    for (int r = 0; r < 4; r++) {
                        accm[i][j][r] += acc[i][j][r];
                        acc[i][j][r] = 0.f;
                    }
        }
        __syncthreads();
    }

    // ---------------- epilogue ----------------
    float d = 0.f, invd = 0.f;
    if (MODE == 0) { d = *dptr; invd = 1.0f / d; }
    #pragma unroll
    for (int mt = 0; mt < 4; mt++) {
        int r0 = m0 + wrow + mt*16 + (lane >> 2);
        #pragma unroll
        for (int nt = 0; nt < 4; nt++) {
            int nc = n0 + wcol + nt*8 + (lane & 3)*2;
            #pragma unroll
            for (int hrow = 0; hrow < 2; hrow++) {
                int rr = r0 + hrow*8;
                if (BOUNDS && rr >= M) continue;
                float c0 = accm[mt][nt][hrow*2+0];
                float c1 = accm[mt][nt][hrow*2+1];
                if (MODE == 0) {
                    int hh = nc >> 6, dd = nc & 63;
                    int b = rr / rows_per_b;
                    int n = rr - b * rows_per_b;
                    char2 pk;
                    pk.x = (char)(int)fminf(fmaxf(rintf(c0 * invd), -128.f), 127.f);
                    pk.y = (char)(int)fminf(fmaxf(rintf(c1 * invd), -128.f), 127.f);
                    *(char2*)(Cq + ((size_t)(b*HH + hh)*rows_per_b + n)*64 + dd) = pk;
                } else {
                    size_t off = (size_t)rr * N + nc;
                    float2 o;
                    o.x = c0 + bias[nc];
                    o.y = c1 + bias[nc+1];
                    if (MODE == 1) {
                        float2 rv = *(const float2*)(res + off);
                        o.x += rv.x; o.y += rv.y;
                    }
                    *(float2*)(Cf + off) = o;
                }
            }
        }
    }
}

// ---------------- int8 scores ----------------
__global__ void __launch_bounds__(256) sim8_kernel(
    const char* __restrict__ Q8, const char* __restrict__ K8,
    float* __restrict__ S, int nk,
    const float* __restrict__ dq, const float* __restrict__ dk)
{
    int bh = blockIdx.z;
    int i0 = blockIdx.y * 64;
    int j0 = blockIdx.x * 64;
    __shared__ int qs[16][68];
    __shared__ int ks[16][68];
    int tid = threadIdx.x;
    int row = tid >> 2;
    int c4  = (tid & 3) * 4;
    {
        int4 qv = *(const int4*)(Q8 + ((size_t)bh*NN + i0 + row)*64 + c4*4);
        qs[c4+0][row]=qv.x; qs[c4+1][row]=qv.y; qs[c4+2][row]=qv.z; qs[c4+3][row]=qv.w;
        int jr = j0 + row;
        int4 kv = make_int4(0,0,0,0);
        if (jr < nk) kv = *(const int4*)(K8 + ((size_t)bh*nk + jr)*64 + c4*4);
        ks[c4+0][row]=kv.x; ks[c4+1][row]=kv.y; ks[c4+2][row]=kv.z; ks[c4+3][row]=kv.w;
    }
    __syncthreads();
    int ty = tid >> 4, tx = tid & 15;
    int acc[4][4];
    #pragma unroll
    for (int i = 0; i < 4; i++)
        #pragma unroll
        for (int j = 0; j < 4; j++) acc[i][j] = 0;
    #pragma unroll
    for (int kk = 0; kk < 16; kk++) {
        int a[4], b[4];
        *(int4*)a = *(const int4*)&qs[kk][ty*4];
        *(int4*)b = *(const int4*)&ks[kk][tx*4];
        #pragma unroll
        for (int i = 0; i < 4; i++)
            #pragma unroll
            for (int j = 0; j < 4; j++) acc[i][j] = __dp4a(a[i], b[j], acc[i][j]);
    }
    float sc = dq[0] * dk[0] * SCALE;
    #pragma unroll
    for (int i = 0; i < 4; i++) {
        size_t ro = ((size_t)bh*NN + i0 + ty*4 + i) * nk;
        #pragma unroll
        for (int j = 0; j < 4; j++) {
            int jj = j0 + tx*4 + j;
            if (jj < nk) S[ro + jj] = (float)acc[i][j] * sc;
        }
    }
}

// ---------------- softmax + weight quant ----------------
__global__ void __launch_bounds__(128) softmax_quant(
    const float* __restrict__ S, unsigned char* __restrict__ W8,
    int cols, int colsp, const float* __restrict__ dptr)
{
    size_t row = blockIdx.x;
    const float* p = S + row * (size_t)cols;
    unsigned char* o = W8 + row * (size_t)colsp;
    int t = threadIdx.x;
    float buf[8];
    int nb = 0;
    float m = -INFINITY;
    for (int c = t; c < cols; c += 128) {
        float v = p[c];
        buf[nb++] = v;
        m = fmaxf(m, v);
    }
    #pragma unroll
    for (int off = 16; off; off >>= 1) m = fmaxf(m, __shfl_xor_sync(0xffffffffu, m, off));
    __shared__ float redm[4], reds[4];
    if ((t & 31) == 0) redm[t >> 5] = m;
    __syncthreads();
    m = fmaxf(fmaxf(redm[0], redm[1]), fmaxf(redm[2], redm[3]));
    float sum = 0.f;
    for (int i = 0; i < nb; i++) { buf[i] = expf(buf[i] - m); sum += buf[i]; }
    #pragma unroll
    for (int off = 16; off; off >>= 1) sum += __shfl_xor_sync(0xffffffffu, sum, off);
    if ((t & 31) == 0) reds[t >> 5] = sum;
    __syncthreads();
    sum = reds[0] + reds[1] + reds[2] + reds[3];
    float inv = 1.0f / sum;
    float invd = 1.0f / dptr[0];
    nb = 0;
    for (int c = t; c < colsp; c += 128) {
        unsigned char ob = 0;
        if (c < cols) {
            float q = rintf(buf[nb++] * inv * invd);
            ob = (unsigned char)(int)fminf(fmaxf(q, 0.f), 255.f);
        }
        o[c] = ob;
    }
}

// ---------------- AV (u8 x s8 dp4a) -> (h,m) planes ----------------
__global__ void __launch_bounds__(256) av8_kernel(
    const unsigned char* __restrict__ W8, const char* __restrict__ V8,
    __half* __restrict__ OH, __half* __restrict__ OM, int nk, int colsp,
    const float* __restrict__ dw, const float* __restrict__ dv)
{
    int bh = blockIdx.y; int b = bh >> 4; int h = bh & 15;
    int i0 = blockIdx.x * 64;
    __shared__ int ws[64][20];
    __shared__ unsigned char vtb[64][76];
    int tid = threadIdx.x;
    int row = tid >> 2;
    int c16 = (tid & 3) * 16;
    int ty = tid >> 4, tx = tid & 15;
    int acc[4][4];
    #pragma unroll
    for (int i = 0; i < 4; i++)
        #pragma unroll
        for (int d = 0; d < 4; d++) acc[i][d] = 0;

    const unsigned char* wb = W8 + ((size_t)bh*NN + i0 + row) * colsp + c16;
    const char* vb = V8 + ((size_t)bh*nk)*64;

    for (int j0 = 0; j0 < nk; j0 += 64) {
        uint4 wv = *(const uint4*)(wb + j0);
        *(uint4*)&ws[row][(tid & 3) * 4] = wv;
        int jr = j0 + row;
        int4 vv = make_int4(0,0,0,0);
        if (jr < nk) vv = *(const int4*)(vb + (size_t)jr*64 + c16);
        union { int4 v; unsigned char bb[16]; } u; u.v = vv;
        #pragma unroll
        for (int i = 0; i < 16; i++) vtb[c16 + i][row] = u.bb[i];
        __syncthreads();
        #pragma unroll
        for (int kk = 0; kk < 16; kk++) {
            int a[4], bb[4];
            #pragma unroll
            for (int i = 0; i < 4; i++) a[i] = ws[ty*4 + i][kk];
            #pragma unroll
            for (int d = 0; d < 4; d++) bb[d] = *(const int*)&vtb[tx*4 + d][kk*4];
            #pragma unroll
            for (int i = 0; i < 4; i++)
                #pragma unroll
                for (int d = 0; d < 4; d++)
                    asm("dp4a.u32.s32 %0, %1, %2, %3;"
                        : "=r"(acc[i][d]) : "r"(a[i]), "r"(bb[d]), "r"(acc[i][d]));
        }
        __syncthreads();
    }
    float sc = dw[0] * dv[0];
    #pragma unroll
    for (int i = 0; i < 4; i++) {
        size_t ro = ((size_t)(b*NN + i0 + ty*4 + i)) * DDIM + h*64 + tx*4;
        ushort4 uh, um;
        __half hh, mm;
        split2((float)acc[i][0] * sc, hh, mm); uh.x=__half_as_ushort(hh); um.x=__half_as_ushort(mm);
        split2((float)acc[i][1] * sc, hh, mm); uh.y=__half_as_ushort(hh); um.y=__half_as_ushort(mm);
        split2((float)acc[i][2] * sc, hh, mm); uh.z=__half_as_ushort(hh); um.z=__half_as_ushort(mm);
        split2((float)acc[i][3] * sc, hh, mm); uh.w=__half_as_ushort(hh); um.w=__half_as_ushort(mm);
        *(ushort4*)&OH[ro] = uh;
        *(ushort4*)&OM[ro] = um;
    }
}

// ---------------- GEGLU -> (h,m) planes ----------------
__global__ void __launch_bounds__(256) geglu_kernel(const float* __restrict__ h,
    __half* __restrict__ AH, __half* __restrict__ AM)
{
    size_t idx = (size_t)blockIdx.x * blockDim.x + threadIdx.x;
    size_t i  = idx / (FFHID / 4);
    size_t c4 = idx % (FFHID / 4);
    float4 a = *(const float4*)(h + i * FFIN + c4 * 4);
    float4 g = *(const float4*)(h + i * FFIN + FFHID + c4 * 4);
    const float kInvSqrt2 = 0.70710678118654752f;
    float o[4];
    o[0] = a.x * (0.5f * g.x * (1.f + erff(g.x * kInvSqrt2)));
    o[1] = a.y * (0.5f * g.y * (1.f + erff(g.y * kInvSqrt2)));
    o[2] = a.z * (0.5f * g.z * (1.f + erff(g.z * kInvSqrt2)));
    o[3] = a.w * (0.5f * g.w * (1.f + erff(g.w * kInvSqrt2)));
    ushort4 uh, um;
    __half hh, mm;
    split2(o[0], hh, mm); uh.x=__half_as_ushort(hh); um.x=__half_as_ushort(mm);
    split2(o[1], hh, mm); uh.y=__half_as_ushort(hh); um.y=__half_as_ushort(mm);
    split2(o[2], hh, mm); uh.z=__half_as_ushort(hh); um.z=__half_as_ushort(mm);
    split2(o[3], hh, mm); uh.w=__half_as_ushort(hh); um.w=__half_as_ushort(mm);
    ((ushort4*)AH)[idx] = uh;
    ((ushort4*)AM)[idx] = um;
}

// ---------------- launch ----------------
extern "C" void kernel_launch(void* const* d_in, const int* in_sizes, int n_in,
                              void* d_out, int out_size)
{
    const float* x    = (const float*)d_in[0];
    const float* ctx  = (const float*)d_in[1];
    const float* n1w  = (const float*)d_in[2];
    const float* n1b  = (const float*)d_in[3];
    const float* n2w  = (const float*)d_in[4];
    const float* n2b  = (const float*)d_in[5];
    const float* n3w  = (const float*)d_in[6];
    const float* n3b  = (const float*)d_in[7];
    const float* a1wq = (const float*)d_in[8];
    const float* a1wk = (const float*)d_in[9];
    const float* a1wv = (const float*)d_in[10];
    const float* a1wo = (const float*)d_in[11];
    const float* a1bo = (const float*)d_in[12];
    const float* a2wq = (const float*)d_in[13];
    const float* a2wk = (const float*)d_in[14];
    const float* a2wv = (const float*)d_in[15];
    const float* a2wo = (const float*)d_in[16];
    const float* a2bo = (const float*)d_in[17];
    const float* ffw1 = (const float*)d_in[18];
    const float* ffb1 = (const float*)d_in[19];
    const float* ffw2 = (const float*)d_in[20];
    const float* ffb2 = (const float*)d_in[21];
    const float* d1q  = (const float*)d_in[22];
    const float* d1k  = (const float*)d_in[23];
    const float* d1v  = (const float*)d_in[24];
    const float* d1w  = (const float*)d_in[25];
    const float* d2q  = (const float*)d_in[26];
    const float* d2k  = (const float*)d_in[27];
    const float* d2v  = (const float*)d_in[28];
    const float* d2w  = (const float*)d_in[29];
    float* out = (float*)d_out;

    float *sim;
    char *q8, *k8, *v8;
    unsigned char *w8;
    __half *ah, *am, *wh, *wm;
    cudaGetSymbolAddress((void**)&sim, g_sim);
    cudaGetSymbolAddress((void**)&q8,  g_q8);
    cudaGetSymbolAddress((void**)&k8,  g_k8);
    cudaGetSymbolAddress((void**)&v8,  g_v8);
    cudaGetSymbolAddress((void**)&w8,  g_w8);
    cudaGetSymbolAddress((void**)&ah,  g_ah);
    cudaGetSymbolAddress((void**)&am,  g_am);
    cudaGetSymbolAddress((void**)&wh,  g_wh);
    cudaGetSymbolAddress((void**)&wm,  g_wm);
    float* hbuf = sim;

    cudaFuncSetAttribute(hgemm<0,false,4>, cudaFuncAttributeMaxDynamicSharedMemorySize, GSMEM);
    cudaFuncSetAttribute(hgemm<0,true ,4>, cudaFuncAttributeMaxDynamicSharedMemorySize, GSMEM);
    cudaFuncSetAttribute(hgemm<1,false,3>, cudaFuncAttributeMaxDynamicSharedMemorySize, GSMEM);
    cudaFuncSetAttribute(hgemm<2,false,3>, cudaFuncAttributeMaxDynamicSharedMemorySize, GSMEM);

    // ---- split all weights (transpose to [N,K]) ----
    wsplit_k<<<dim3(DDIM/32, DDIM/32), 256>>>(a1wq, wh+OFF_WQ1, wm+OFF_WQ1, DDIM, DDIM);
    wsplit_k<<<dim3(DDIM/32, DDIM/32), 256>>>(a1wk, wh+OFF_WK1, wm+OFF_WK1, DDIM, DDIM);
    wsplit_k<<<dim3(DDIM/32, DDIM/32), 256>>>(a1wv, wh+OFF_WV1, wm+OFF_WV1, DDIM, DDIM);
    wsplit_k<<<dim3(DDIM/32, DDIM/32), 256>>>(a1wo, wh+OFF_WO1, wm+OFF_WO1, DDIM, DDIM);
    wsplit_k<<<dim3(DDIM/32, DDIM/32), 256>>>(a2wq, wh+OFF_WQ2, wm+OFF_WQ2, DDIM, DDIM);
    wsplit_k<<<dim3(DDIM/32, DDIM/32), 256>>>(a2wo, wh+OFF_WO2, wm+OFF_WO2, DDIM, DDIM);
    wsplit_k<<<dim3(DDIM/32, CTXD/32), 256>>>(a2wk, wh+OFF_WK2, wm+OFF_WK2, CTXD, DDIM);
    wsplit_k<<<dim3(DDIM/32, CTXD/32), 256>>>(a2wv, wh+OFF_WV2, wm+OFF_WV2, CTXD, DDIM);
    wsplit_k<<<dim3(FFIN/32, DDIM/32), 256>>>(ffw1, wh+OFF_FF1, wm+OFF_FF1, DDIM, FFIN);
    wsplit_k<<<dim3(DDIM/32, FFHID/32), 256>>>(ffw2, wh+OFF_FF2, wm+OFF_FF2, FFHID, DDIM);

    // ---- attn1 (self) ----
    ln_kernel<<<TOK, 256>>>(x, n1w, n1b, ah, am);
    hgemm<0,false,4><<<dim3(8,32), 256, GSMEM>>>(ah,am, wh+OFF_WQ1,wm+OFF_WQ1,
        nullptr, nullptr, nullptr, q8, TOK, DDIM, DDIM, d1q, NN);
    hgemm<0,false,4><<<dim3(8,32), 256, GSMEM>>>(ah,am, wh+OFF_WK1,wm+OFF_WK1,
        nullptr, nullptr, nullptr, k8, TOK, DDIM, DDIM, d1k, NN);
    hgemm<0,false,4><<<dim3(8,32), 256, GSMEM>>>(ah,am, wh+OFF_WV1,wm+OFF_WV1,
        nullptr, nullptr, nullptr, v8, TOK, DDIM, DDIM, d1v, NN);
    sim8_kernel<<<dim3(16,16,BB*HH), 256>>>(q8, k8, sim, NN, d1q, d1k);
    softmax_quant<<<BB*HH*NN, 128>>>(sim, w8, NN, NN, d1w);
    av8_kernel<<<dim3(16,BB*HH), 256>>>(w8, v8, ah, am, NN, NN, d1w, d1v);
    hgemm<1,false,3><<<dim3(8,32), 256, GSMEM>>>(ah,am, wh+OFF_WO1,wm+OFF_WO1,
        a1bo, x, out, nullptr, TOK, DDIM, DDIM, nullptr, 0);

    // ---- attn2 (cross) ----
    ln_kernel<<<TOK, 256>>>(out, n2w, n2b, ah, am);
    hgemm<0,false,4><<<dim3(8,32), 256, GSMEM>>>(ah,am, wh+OFF_WQ2,wm+OFF_WQ2,
        nullptr, nullptr, nullptr, q8, TOK, DDIM, DDIM, d2q, NN);
    asplit_k<<<(CTOK*CTXD/4 + 255)/256, 256>>>(ctx, ah, am, CTOK*CTXD/4);
    hgemm<0,true ,4><<<dim3(8,3), 256, GSMEM>>>(ah,am, wh+OFF_WK2,wm+OFF_WK2,
        nullptr, nullptr, nullptr, k8, CTOK, DDIM, CTXD, d2k, CTXN);
    hgemm<0,true ,4><<<dim3(8,3), 256, GSMEM>>>(ah,am, wh+OFF_WV2,wm+OFF_WV2,
        nullptr, nullptr, nullptr, v8, CTOK, DDIM, CTXD, d2v, CTXN);
    sim8_kernel<<<dim3(2,16,BB*HH), 256>>>(q8, k8, sim, CTXN, d2q, d2k);
    softmax_quant<<<BB*HH*NN, 128>>>(sim, w8, CTXN, 128, d2w);
    av8_kernel<<<dim3(16,BB*HH), 256>>>(w8, v8, ah, am, CTXN, 128, d2w, d2v);
    hgemm<1,false,3><<<dim3(8,32), 256, GSMEM>>>(ah,am, wh+OFF_WO2,wm+OFF_WO2,
        a2bo, out, out, nullptr, TOK, DDIM, DDIM, nullptr, 0);

    // ---- GEGLU FF ----
    ln_kernel<<<TOK, 256>>>(out, n3w, n3b, ah, am);
    hgemm<2,false,3><<<dim3(64,32), 256, GSMEM>>>(ah,am, wh+OFF_FF1,wm+OFF_FF1,
        ffb1, nullptr, hbuf, nullptr, TOK, FFIN, DDIM, nullptr, 0);
    geglu_kernel<<<(TOK*(FFHID/4))/256, 256>>>(hbuf, ah, am);
    hgemm<1,false,3><<<dim3(8,32), 256, GSMEM>>>(ah,am, wh+OFF_FF2,wm+OFF_FF2,
        ffb2, out, out, nullptr, TOK, DDIM, FFHID, nullptr, 0);
}

// round 8
// speedup vs baseline: 1.8930x; 1.2940x over previous
#include <cuda_runtime.h>
#include <cuda_fp16.h>
#include <math.h>
#include <stdint.h>

// ---------------- problem constants ----------------
#define BB 4
#define NN 1024
#define DDIM 1024
#define HH 16
#define CTXN 77
#define CTXD 768
#define FFIN 8192
#define FFHID 4096
#define TOK (BB*NN)      // 4096
#define CTOK (BB*CTXN)   // 308
#define SCALE 0.125f
#define RSC 2048.0f      // residual plane scale (2^11)
#define RSCINV (1.0f/2048.0f)

// ---------------- scratch (device globals) ----------------
__device__ char  g_q8[(size_t)TOK*DDIM];
__device__ char  g_k8[(size_t)TOK*DDIM];
__device__ char  g_v8[(size_t)TOK*DDIM];
__device__ unsigned char g_w8[(size_t)BB*HH*NN*NN];
__device__ float g_sim[(size_t)BB*HH*NN*NN];   // scores; reused for FF hidden

// activation half-split planes (max 4096x4096)
#define AMAX ((size_t)TOK*FFHID)
__device__ __half g_ah[AMAX];
__device__ __half g_am[AMAX];

// weight split planes, concatenated [N,K] layouts
#define OFF_WQ1  ((size_t)0)
#define OFF_WK1  ((size_t)1048576)
#define OFF_WV1  ((size_t)2097152)
#define OFF_WO1  ((size_t)3145728)
#define OFF_WQ2  ((size_t)4194304)
#define OFF_WO2  ((size_t)5242880)
#define OFF_WK2  ((size_t)6291456)
#define OFF_WV2  ((size_t)(6291456+786432))
#define OFF_FF1  ((size_t)(6291456+1572864))
#define OFF_FF2  ((size_t)(OFF_FF1+8388608))
#define WTOT     ((size_t)(OFF_FF2+4194304))
__device__ __half g_wh[WTOT];
__device__ __half g_wm[WTOT];

// ---------------- helpers ----------------
__device__ __forceinline__ uint32_t smem_u32(const void* p) {
    uint32_t a;
    asm("{ .reg .u64 t; cvta.to.shared.u64 t, %1; cvt.u32.u64 %0, t; }" : "=r"(a) : "l"(p));
    return a;
}
__device__ __forceinline__ void cpasync16(uint32_t s, const void* g, int sz) {
    asm volatile("cp.async.cg.shared.global [%0], [%1], 16, %2;"
                 :: "r"(s), "l"(g), "r"(sz));
}
__device__ __forceinline__ void cpcommit() { asm volatile("cp.async.commit_group;"); }
__device__ __forceinline__ void cpwait2()  { asm volatile("cp.async.wait_group 2;"); }

// scaled split: x ~= h + m/2048, with m in fp16 normal range
__device__ __forceinline__ void split2(float x, __half& h, __half& m) {
    h = __float2half_rn(x);
    m = __float2half_rn((x - __half2float(h)) * RSC);
}

// ---------------- LayerNorm -> (h,m) planes ----------------
__global__ void __launch_bounds__(256) ln_kernel(const float* __restrict__ x,
    const float* __restrict__ w, const float* __restrict__ b,
    __half* __restrict__ H, __half* __restrict__ Mp)
{
    int row = blockIdx.x;
    int t = threadIdx.x;
    const float4* xr = (const float4*)(x + (size_t)row * DDIM);
    float4 v = xr[t];
    float s  = v.x + v.y + v.z + v.w;
    float ss = v.x*v.x + v.y*v.y + v.z*v.z + v.w*v.w;
    #pragma unroll
    for (int o = 16; o; o >>= 1) {
        s  += __shfl_xor_sync(0xffffffffu, s, o);
        ss += __shfl_xor_sync(0xffffffffu, ss, o);
    }
    __shared__ float sh_s[8], sh_q[8];
    int wid = t >> 5, lane = t & 31;
    if (lane == 0) { sh_s[wid] = s; sh_q[wid] = ss; }
    __syncthreads();
    if (t == 0) {
        float a = 0.f, c = 0.f;
        #pragma unroll
        for (int i = 0; i < 8; i++) { a += sh_s[i]; c += sh_q[i]; }
        float m = a * (1.0f/DDIM);
        float var = c * (1.0f/DDIM) - m*m;
        sh_s[0] = m;
        sh_q[0] = rsqrtf(var + 1e-5f);
    }
    __syncthreads();
    float m = sh_s[0], r = sh_q[0];
    float4 wv = ((const float4*)w)[t];
    float4 bv = ((const float4*)b)[t];
    float o[4];
    o[0] = (v.x - m) * r * wv.x + bv.x;
    o[1] = (v.y - m) * r * wv.y + bv.y;
    o[2] = (v.z - m) * r * wv.z + bv.z;
    o[3] = (v.w - m) * r * wv.w + bv.w;
    ushort4 uh, um;
    __half h0, m0;
    split2(o[0], h0, m0); uh.x = __half_as_ushort(h0); um.x = __half_as_ushort(m0);
    split2(o[1], h0, m0); uh.y = __half_as_ushort(h0); um.y = __half_as_ushort(m0);
    split2(o[2], h0, m0); uh.z = __half_as_ushort(h0); um.z = __half_as_ushort(m0);
    split2(o[3], h0, m0); uh.w = __half_as_ushort(h0); um.w = __half_as_ushort(m0);
    ((ushort4*)(H  + (size_t)row * DDIM))[t] = uh;
    ((ushort4*)(Mp + (size_t)row * DDIM))[t] = um;
}

// ---------------- activation split (ctx only) ----------------
__global__ void __launch_bounds__(256) asplit_k(const float* __restrict__ A,
    __half* __restrict__ H, __half* __restrict__ Mp, int n4)
{
    int i = blockIdx.x * 256 + threadIdx.x;
    if (i >= n4) return;
    float4 v = ((const float4*)A)[i];
    ushort4 uh, um;
    __half h0, m0;
    split2(v.x, h0, m0); uh.x = __half_as_ushort(h0); um.x = __half_as_ushort(m0);
    split2(v.y, h0, m0); uh.y = __half_as_ushort(h0); um.y = __half_as_ushort(m0);
    split2(v.z, h0, m0); uh.z = __half_as_ushort(h0); um.z = __half_as_ushort(m0);
    split2(v.w, h0, m0); uh.w = __half_as_ushort(h0); um.w = __half_as_ushort(m0);
    ((ushort4*)H)[i] = uh; ((ushort4*)Mp)[i] = um;
}

// ---------------- weight transpose+split (batched) ----------------
// W[K,N] fp32 -> [N,K] half x2 at out offset. z selects source/offset.
struct WS6 { const float* w[6]; };

__device__ __forceinline__ void wsplit_body(const float* __restrict__ W,
    __half* __restrict__ H, __half* __restrict__ Mp, int K, int N)
{
    __shared__ float tile[32][33];
    int n0 = blockIdx.x * 32, k0 = blockIdx.y * 32;
    int tx = threadIdx.x & 31, ty = threadIdx.x >> 5;
    #pragma unroll
    for (int i = 0; i < 4; i++)
        tile[ty + i*8][tx] = W[(size_t)(k0 + ty + i*8) * N + n0 + tx];
    __syncthreads();
    #pragma unroll
    for (int i = 0; i < 4; i++) {
        int nl = ty + i*8;
        float x = tile[tx][nl];
        __half h, m;
        split2(x, h, m);
        size_t o = (size_t)(n0 + nl) * K + k0 + tx;
        H[o] = h; Mp[o] = m;
    }
}

__global__ void __launch_bounds__(256) wsplit6_k(WS6 ws,
    __half* __restrict__ H, __half* __restrict__ Mp)
{
    int z = blockIdx.z;
    size_t off = (size_t)z * 1048576;
    wsplit_body(ws.w[z], H + off, Mp + off, DDIM, DDIM);
}

__global__ void __launch_bounds__(256) wsplit_ctx2_k(const float* __restrict__ wk,
    const float* __restrict__ wv, __half* __restrict__ H, __half* __restrict__ Mp)
{
    int z = blockIdx.z;
    const float* W = z ? wv : wk;
    size_t off = OFF_WK2 + (size_t)z * 786432;
    wsplit_body(W, H + off, Mp + off, CTXD, DDIM);
}

__global__ void __launch_bounds__(256) wsplit1_k(const float* __restrict__ W,
    __half* __restrict__ H, __half* __restrict__ Mp, int K, int N)
{
    wsplit_body(W, H, Mp, K, N);
}

// ---------------- HMMA GEMM: D[M,N] = A[M,K] @ T[N,K]^T, 3-term fp16 split -
// Dual accumulators: mma tile-acc flushed into fp32 master (RN FADD) every 2
// iterations to break tensor-core RZ accumulation bias.
// Terms: (h,m'), (m',h) [scaled x2048] -> rescale -> (h,h)
// 4-stage cp.async pipeline, prefetch distance 2, ONE barrier per iteration.
#define BM 128
#define BN 128
#define BK 32
#define ROWB 80
#define ATILE (BM*ROWB)
#define STAGEB (2*ATILE)
#define NSTAGE 4
#define GSMEM (NSTAGE*STAGEB)

template<int MODE, bool BOUNDS>
__global__ void __launch_bounds__(256, 1) hgemm(
    const __half* __restrict__ Ah, const __half* __restrict__ Am,
    const __half* __restrict__ Bh, const __half* __restrict__ Bm,
    const float* __restrict__ bias, const float* __restrict__ res,
    float* __restrict__ Cf, char* __restrict__ Cq,
    int M, int N, int K, const float* __restrict__ dptr, int rows_per_b)
{
    extern __shared__ char smem[];
    const uint32_t sb = smem_u32(smem);
    const int tid  = threadIdx.x;
    const int wid  = tid >> 5;
    const int lane = tid & 31;
    const int m0 = blockIdx.y * BM;
    const int n0 = blockIdx.x * BN;
    const int wrow = (wid >> 2) * 64;
    const int wcol = (wid & 3) * 32;

    const int KT32 = K >> 5;
    const int T = 3 * KT32;   // even for our shapes

    const __half* APL[3] = { Ah, Am, Ah };
    const __half* BPL[3] = { Bm, Bh, Bh };

    int lkt = 0, lterm = 0;
    const __half* lpa = APL[0];
    const __half* lpb = BPL[0];

    const int arow = tid >> 1;
    const int aco  = (tid & 1) * 32;
    int grow = m0 + arow;
    if (BOUNDS && grow >= M) grow = M - 1;
    const int asz = (!BOUNDS || (m0 + arow) < M) ? 16 : 0;

    auto issue = [&](int buf) {
        const char* ga = (const char*)lpa + (((size_t)grow*K + lkt*BK) << 1) + aco;
        uint32_t sa = sb + buf*STAGEB + arow*ROWB + aco;
        cpasync16(sa,      ga,      asz);
        cpasync16(sa + 16, ga + 16, asz);
        const char* gb = (const char*)lpb + (((size_t)(n0+arow)*K + lkt*BK) << 1) + aco;
        uint32_t sbb = sb + buf*STAGEB + ATILE + arow*ROWB + aco;
        cpasync16(sbb,      gb,      16);
        cpasync16(sbb + 16, gb + 16, 16);
    };
    auto adv = [&]() {
        if (++lkt == KT32) {
            lkt = 0;
            ++lterm;
            int tt = lterm < 3 ? lterm : 2;
            lpa = APL[tt];
            lpb = BPL[tt];
        }
    };

    float acc[4][4][4];    // mma tile accumulator (short RZ chains)
    float accm[4][4][4];   // fp32 master accumulator (RN adds)
    #pragma unroll
    for (int i = 0; i < 4; i++)
        #pragma unroll
        for (int j = 0; j < 4; j++)
            #pragma unroll
            for (int r = 0; r < 4; r++) { acc[i][j][r] = 0.f; accm[i][j][r] = 0.f; }

    issue(0); adv(); cpcommit();
    issue(1); adv(); cpcommit();

    for (int it = 0; it < T; it++) {
        if (it + 2 < T) { issue((it + 2) % NSTAGE); adv(); }
        cpcommit();
        cpwait2();
        __syncthreads();
        // rescale point is even `it`; tile acc is zero there (flushed at odd it)
        if (it == 2*KT32) {
            #pragma unroll
            for (int i = 0; i < 4; i++)
                #pragma unroll
                for (int j = 0; j < 4; j++)
                    #pragma unroll
                    for (int r = 0; r < 4; r++) accm[i][j][r] *= RSCINV;
        }
        const uint32_t abase = sb + (it % NSTAGE) * STAGEB;
        const uint32_t bbase = abase + ATILE;
        #pragma unroll
        for (int kh = 0; kh < 2; kh++) {
            uint32_t b0[4], b1[4];
            #pragma unroll
            for (int nt = 0; nt < 4; nt++) {
                uint32_t ad = bbase + (wcol + nt*8 + (lane & 7))*ROWB
                            + kh*32 + ((lane >> 3) & 1)*16;
                asm volatile("ldmatrix.sync.aligned.m8n8.x2.shared.b16 {%0,%1}, [%2];"
                             : "=r"(b0[nt]), "=r"(b1[nt]) : "r"(ad));
            }
            #pragma unroll
            for (int mt = 0; mt < 4; mt++) {
                uint32_t a0, a1, a2, a3;
                uint32_t ad = abase + (wrow + mt*16 + ((lane >> 3) & 1)*8 + (lane & 7))*ROWB
                            + kh*32 + ((lane >> 4) & 1)*16;
                asm volatile("ldmatrix.sync.aligned.m8n8.x4.shared.b16 {%0,%1,%2,%3}, [%4];"
                             : "=r"(a0), "=r"(a1), "=r"(a2), "=r"(a3) : "r"(ad));
                #pragma unroll
                for (int nt = 0; nt < 4; nt++) {
                    asm volatile(
                        "mma.sync.aligned.m16n8k16.row.col.f32.f16.f16.f32 "
                        "{%0,%1,%2,%3}, {%4,%5,%6,%7}, {%8,%9}, {%0,%1,%2,%3};"
                        : "+f"(acc[mt][nt][0]), "+f"(acc[mt][nt][1]),
                          "+f"(acc[mt][nt][2]), "+f"(acc[mt][nt][3])
                        : "r"(a0), "r"(a1), "r"(a2), "r"(a3), "r"(b0[nt]), "r"(b1[nt]));
                }
            }
        }
        if (it & 1) {
            // flush tile acc into master with RN adds; restart RZ chain
            #pragma unroll
            for (int i = 0; i < 4; i++)
                #pragma unroll
                for (int j = 0; j < 4; j++)
                    #pragma unroll
                    for (int r = 0; r < 4; r++) {
                        accm[i][j][r] += acc[i][j][r];
                        acc[i][j][r] = 0.f;
                    }
        }
    }

    // ---------------- epilogue ----------------
    float d = 0.f, invd = 0.f;
    if (MODE == 0) { d = *dptr; invd = 1.0f / d; }
    #pragma unroll
    for (int mt = 0; mt < 4; mt++) {
        int r0 = m0 + wrow + mt*16 + (lane >> 2);
        #pragma unroll
        for (int nt = 0; nt < 4; nt++) {
            int nc = n0 + wcol + nt*8 + (lane & 3)*2;
            #pragma unroll
            for (int hrow = 0; hrow < 2; hrow++) {
                int rr = r0 + hrow*8;
                if (BOUNDS && rr >= M) continue;
                float c0 = accm[mt][nt][hrow*2+0];
                float c1 = accm[mt][nt][hrow*2+1];
                if (MODE == 0) {
                    int hh = nc >> 6, dd = nc & 63;
                    int b = rr / rows_per_b;
                    int n = rr - b * rows_per_b;
                    char2 pk;
                    pk.x = (char)(int)fminf(fmaxf(rintf(c0 * invd), -128.f), 127.f);
                    pk.y = (char)(int)fminf(fmaxf(rintf(c1 * invd), -128.f), 127.f);
                    *(char2*)(Cq + ((size_t)(b*HH + hh)*rows_per_b + n)*64 + dd) = pk;
                } else {
                    size_t off = (size_t)rr * N + nc;
                    float2 o;
                    o.x = c0 + bias[nc];
                    o.y = c1 + bias[nc+1];
                    if (MODE == 1) {
                        float2 rv = *(const float2*)(res + off);
                        o.x += rv.x; o.y += rv.y;
                    }
                    *(float2*)(Cf + off) = o;
                }
            }
        }
    }
}

// ---------------- int8 scores ----------------
__global__ void __launch_bounds__(256) sim8_kernel(
    const char* __restrict__ Q8, const char* __restrict__ K8,
    float* __restrict__ S, int nk,
    const float* __restrict__ dq, const float* __restrict__ dk)
{
    int bh = blockIdx.z;
    int i0 = blockIdx.y * 64;
    int j0 = blockIdx.x * 64;
    __shared__ int qs[16][68];
    __shared__ int ks[16][68];
    int tid = threadIdx.x;
    int row = tid >> 2;
    int c4  = (tid & 3) * 4;
    {
        int4 qv = *(const int4*)(Q8 + ((size_t)bh*NN + i0 + row)*64 + c4*4);
        qs[c4+0][row]=qv.x; qs[c4+1][row]=qv.y; qs[c4+2][row]=qv.z; qs[c4+3][row]=qv.w;
        int jr = j0 + row;
        int4 kv = make_int4(0,0,0,0);
        if (jr < nk) kv = *(const int4*)(K8 + ((size_t)bh*nk + jr)*64 + c4*4);
        ks[c4+0][row]=kv.x; ks[c4+1][row]=kv.y; ks[c4+2][row]=kv.z; ks[c4+3][row]=kv.w;
    }
    __syncthreads();
    int ty = tid >> 4, tx = tid & 15;
    int acc[4][4];
    #pragma unroll
    for (int i = 0; i < 4; i++)
        #pragma unroll
        for (int j = 0; j < 4; j++) acc[i][j] = 0;
    #pragma unroll
    for (int kk = 0; kk < 16; kk++) {
        int a[4], b[4];
        *(int4*)a = *(const int4*)&qs[kk][ty*4];
        *(int4*)b = *(const int4*)&ks[kk][tx*4];
        #pragma unroll
        for (int i = 0; i < 4; i++)
            #pragma unroll
            for (int j = 0; j < 4; j++) acc[i][j] = __dp4a(a[i], b[j], acc[i][j]);
    }
    float sc = dq[0] * dk[0] * SCALE;
    #pragma unroll
    for (int i = 0; i < 4; i++) {
        size_t ro = ((size_t)bh*NN + i0 + ty*4 + i) * nk;
        #pragma unroll
        for (int j = 0; j < 4; j++) {
            int jj = j0 + tx*4 + j;
            if (jj < nk) S[ro + jj] = (float)acc[i][j] * sc;
        }
    }
}

// ---------------- softmax + weight quant ----------------
__global__ void __launch_bounds__(128) softmax_quant(
    const float* __restrict__ S, unsigned char* __restrict__ W8,
    int cols, int colsp, const float* __restrict__ dptr)
{
    size_t row = blockIdx.x;
    const float* p = S + row * (size_t)cols;
    unsigned char* o = W8 + row * (size_t)colsp;
    int t = threadIdx.x;
    float buf[8];
    int nb = 0;
    float m = -INFINITY;
    for (int c = t; c < cols; c += 128) {
        float v = p[c];
        buf[nb++] = v;
        m = fmaxf(m, v);
    }
    #pragma unroll
    for (int off = 16; off; off >>= 1) m = fmaxf(m, __shfl_xor_sync(0xffffffffu, m, off));
    __shared__ float redm[4], reds[4];
    if ((t & 31) == 0) redm[t >> 5] = m;
    __syncthreads();
    m = fmaxf(fmaxf(redm[0], redm[1]), fmaxf(redm[2], redm[3]));
    float sum = 0.f;
    for (int i = 0; i < nb; i++) { buf[i] = expf(buf[i] - m); sum += buf[i]; }
    #pragma unroll
    for (int off = 16; off; off >>= 1) sum += __shfl_xor_sync(0xffffffffu, sum, off);
    if ((t & 31) == 0) reds[t >> 5] = sum;
    __syncthreads();
    sum = reds[0] + reds[1] + reds[2] + reds[3];
    float inv = 1.0f / sum;
    float invd = 1.0f / dptr[0];
    nb = 0;
    for (int c = t; c < colsp; c += 128) {
        unsigned char ob = 0;
        if (c < cols) {
            float q = rintf(buf[nb++] * inv * invd);
            ob = (unsigned char)(int)fminf(fmaxf(q, 0.f), 255.f);
        }
        o[c] = ob;
    }
}

// ---------------- AV (u8 x s8 dp4a) -> (h,m) planes ----------------
__global__ void __launch_bounds__(256) av8_kernel(
    const unsigned char* __restrict__ W8, const char* __restrict__ V8,
    __half* __restrict__ OH, __half* __restrict__ OM, int nk, int colsp,
    const float* __restrict__ dw, const float* __restrict__ dv)
{
    int bh = blockIdx.y; int b = bh >> 4; int h = bh & 15;
    int i0 = blockIdx.x * 64;
    __shared__ int ws[64][20];
    __shared__ unsigned char vtb[64][76];
    int tid = threadIdx.x;
    int row = tid >> 2;
    int c16 = (tid & 3) * 16;
    int ty = tid >> 4, tx = tid & 15;
    int acc[4][4];
    #pragma unroll
    for (int i = 0; i < 4; i++)
        #pragma unroll
        for (int d = 0; d < 4; d++) acc[i][d] = 0;

    const unsigned char* wb = W8 + ((size_t)bh*NN + i0 + row) * colsp + c16;
    const char* vb = V8 + ((size_t)bh*nk)*64;

    for (int j0 = 0; j0 < nk; j0 += 64) {
        uint4 wv = *(const uint4*)(wb + j0);
        *(uint4*)&ws[row][(tid & 3) * 4] = wv;
        int jr = j0 + row;
        int4 vv = make_int4(0,0,0,0);
        if (jr < nk) vv = *(const int4*)(vb + (size_t)jr*64 + c16);
        union { int4 v; unsigned char bb[16]; } u; u.v = vv;
        #pragma unroll
        for (int i = 0; i < 16; i++) vtb[c16 + i][row] = u.bb[i];
        __syncthreads();
        #pragma unroll
        for (int kk = 0; kk < 16; kk++) {
            int a[4], bb[4];
            #pragma unroll
            for (int i = 0; i < 4; i++) a[i] = ws[ty*4 + i][kk];
            #pragma unroll
            for (int d = 0; d < 4; d++) bb[d] = *(const int*)&vtb[tx*4 + d][kk*4];
            #pragma unroll
            for (int i = 0; i < 4; i++)
                #pragma unroll
                for (int d = 0; d < 4; d++)
                    asm("dp4a.u32.s32 %0, %1, %2, %3;"
                        : "=r"(acc[i][d]) : "r"(a[i]), "r"(bb[d]), "r"(acc[i][d]));
        }
        __syncthreads();
    }
    float sc = dw[0] * dv[0];
    #pragma unroll
    for (int i = 0; i < 4; i++) {
        size_t ro = ((size_t)(b*NN + i0 + ty*4 + i)) * DDIM + h*64 + tx*4;
        ushort4 uh, um;
        __half hh, mm;
        split2((float)acc[i][0] * sc, hh, mm); uh.x=__half_as_ushort(hh); um.x=__half_as_ushort(mm);
        split2((float)acc[i][1] * sc, hh, mm); uh.y=__half_as_ushort(hh); um.y=__half_as_ushort(mm);
        split2((float)acc[i][2] * sc, hh, mm); uh.z=__half_as_ushort(hh); um.z=__half_as_ushort(mm);
        split2((float)acc[i][3] * sc, hh, mm); uh.w=__half_as_ushort(hh); um.w=__half_as_ushort(mm);
        *(ushort4*)&OH[ro] = uh;
        *(ushort4*)&OM[ro] = um;
    }
}

// ---------------- GEGLU -> (h,m) planes ----------------
__global__ void __launch_bounds__(256) geglu_kernel(const float* __restrict__ h,
    __half* __restrict__ AH, __half* __restrict__ AM)
{
    size_t idx = (size_t)blockIdx.x * blockDim.x + threadIdx.x;
    size_t i  = idx / (FFHID / 4);
    size_t c4 = idx % (FFHID / 4);
    float4 a = *(const float4*)(h + i * FFIN + c4 * 4);
    float4 g = *(const float4*)(h + i * FFIN + FFHID + c4 * 4);
    const float kInvSqrt2 = 0.70710678118654752f;
    float o[4];
    o[0] = a.x * (0.5f * g.x * (1.f + erff(g.x * kInvSqrt2)));
    o[1] = a.y * (0.5f * g.y * (1.f + erff(g.y * kInvSqrt2)));
    o[2] = a.z * (0.5f * g.z * (1.f + erff(g.z * kInvSqrt2)));
    o[3] = a.w * (0.5f * g.w * (1.f + erff(g.w * kInvSqrt2)));
    ushort4 uh, um;
    __half hh, mm;
    split2(o[0], hh, mm); uh.x=__half_as_ushort(hh); um.x=__half_as_ushort(mm);
    split2(o[1], hh, mm); uh.y=__half_as_ushort(hh); um.y=__half_as_ushort(mm);
    split2(o[2], hh, mm); uh.z=__half_as_ushort(hh); um.z=__half_as_ushort(mm);
    split2(o[3], hh, mm); uh.w=__half_as_ushort(hh); um.w=__half_as_ushort(mm);
    ((ushort4*)AH)[idx] = uh;
    ((ushort4*)AM)[idx] = um;
}

// ---------------- launch ----------------
extern "C" void kernel_launch(void* const* d_in, const int* in_sizes, int n_in,
                              void* d_out, int out_size)
{
    const float* x    = (const float*)d_in[0];
    const float* ctx  = (const float*)d_in[1];
    const float* n1w  = (const float*)d_in[2];
    const float* n1b  = (const float*)d_in[3];
    const float* n2w  = (const float*)d_in[4];
    const float* n2b  = (const float*)d_in[5];
    const float* n3w  = (const float*)d_in[6];
    const float* n3b  = (const float*)d_in[7];
    const float* a1wq = (const float*)d_in[8];
    const float* a1wk = (const float*)d_in[9];
    const float* a1wv = (const float*)d_in[10];
    const float* a1wo = (const float*)d_in[11];
    const float* a1bo = (const float*)d_in[12];
    const float* a2wq = (const float*)d_in[13];
    const float* a2wk = (const float*)d_in[14];
    const float* a2wv = (const float*)d_in[15];
    const float* a2wo = (const float*)d_in[16];
    const float* a2bo = (const float*)d_in[17];
    const float* ffw1 = (const float*)d_in[18];
    const float* ffb1 = (const float*)d_in[19];
    const float* ffw2 = (const float*)d_in[20];
    const float* ffb2 = (const float*)d_in[21];
    const float* d1q  = (const float*)d_in[22];
    const float* d1k  = (const float*)d_in[23];
    const float* d1v  = (const float*)d_in[24];
    const float* d1w  = (const float*)d_in[25];
    const float* d2q  = (const float*)d_in[26];
    const float* d2k  = (const float*)d_in[27];
    const float* d2v  = (const float*)d_in[28];
    const float* d2w  = (const float*)d_in[29];
    float* out = (float*)d_out;

    float *sim;
    char *q8, *k8, *v8;
    unsigned char *w8;
    __half *ah, *am, *wh, *wm;
    cudaGetSymbolAddress((void**)&sim, g_sim);
    cudaGetSymbolAddress((void**)&q8,  g_q8);
    cudaGetSymbolAddress((void**)&k8,  g_k8);
    cudaGetSymbolAddress((void**)&v8,  g_v8);
    cudaGetSymbolAddress((void**)&w8,  g_w8);
    cudaGetSymbolAddress((void**)&ah,  g_ah);
    cudaGetSymbolAddress((void**)&am,  g_am);
    cudaGetSymbolAddress((void**)&wh,  g_wh);
    cudaGetSymbolAddress((void**)&wm,  g_wm);
    float* hbuf = sim;

    cudaFuncSetAttribute(hgemm<0,false>, cudaFuncAttributeMaxDynamicSharedMemorySize, GSMEM);
    cudaFuncSetAttribute(hgemm<0,true >, cudaFuncAttributeMaxDynamicSharedMemorySize, GSMEM);
    cudaFuncSetAttribute(hgemm<1,false>, cudaFuncAttributeMaxDynamicSharedMemorySize, GSMEM);
    cudaFuncSetAttribute(hgemm<2,false>, cudaFuncAttributeMaxDynamicSharedMemorySize, GSMEM);

    // ---- split all weights (batched; 4 launches) ----
    WS6 ws6;
    ws6.w[0] = a1wq; ws6.w[1] = a1wk; ws6.w[2] = a1wv;
    ws6.w[3] = a1wo; ws6.w[4] = a2wq; ws6.w[5] = a2wo;
    wsplit6_k<<<dim3(DDIM/32, DDIM/32, 6), 256>>>(ws6, wh, wm);
    wsplit_ctx2_k<<<dim3(DDIM/32, CTXD/32, 2), 256>>>(a2wk, a2wv, wh, wm);
    wsplit1_k<<<dim3(FFIN/32, DDIM/32), 256>>>(ffw1, wh+OFF_FF1, wm+OFF_FF1, DDIM, FFIN);
    wsplit1_k<<<dim3(DDIM/32, FFHID/32), 256>>>(ffw2, wh+OFF_FF2, wm+OFF_FF2, FFHID, DDIM);

    // ---- attn1 (self) ----
    ln_kernel<<<TOK, 256>>>(x, n1w, n1b, ah, am);
    hgemm<0,false><<<dim3(8,32), 256, GSMEM>>>(ah,am, wh+OFF_WQ1,wm+OFF_WQ1,
        nullptr, nullptr, nullptr, q8, TOK, DDIM, DDIM, d1q, NN);
    hgemm<0,false><<<dim3(8,32), 256, GSMEM>>>(ah,am, wh+OFF_WK1,wm+OFF_WK1,
        nullptr, nullptr, nullptr, k8, TOK, DDIM, DDIM, d1k, NN);
    hgemm<0,false><<<dim3(8,32), 256, GSMEM>>>(ah,am, wh+OFF_WV1,wm+OFF_WV1,
        nullptr, nullptr, nullptr, v8, TOK, DDIM, DDIM, d1v, NN);
    sim8_kernel<<<dim3(16,16,BB*HH), 256>>>(q8, k8, sim, NN, d1q, d1k);
    softmax_quant<<<BB*HH*NN, 128>>>(sim, w8, NN, NN, d1w);
    av8_kernel<<<dim3(16,BB*HH), 256>>>(w8, v8, ah, am, NN, NN, d1w, d1v);
    hgemm<1,false><<<dim3(8,32), 256, GSMEM>>>(ah,am, wh+OFF_WO1,wm+OFF_WO1,
        a1bo, x, out, nullptr, TOK, DDIM, DDIM, nullptr, 0);

    // ---- attn2 (cross) ----
    ln_kernel<<<TOK, 256>>>(out, n2w, n2b, ah, am);
    hgemm<0,false><<<dim3(8,32), 256, GSMEM>>>(ah,am, wh+OFF_WQ2,wm+OFF_WQ2,
        nullptr, nullptr, nullptr, q8, TOK, DDIM, DDIM, d2q, NN);
    asplit_k<<<(CTOK*CTXD/4 + 255)/256, 256>>>(ctx, ah, am, CTOK*CTXD/4);
    hgemm<0,true ><<<dim3(8,3), 256, GSMEM>>>(ah,am, wh+OFF_WK2,wm+OFF_WK2,
        nullptr, nullptr, nullptr, k8, CTOK, DDIM, CTXD, d2k, CTXN);
    hgemm<0,true ><<<dim3(8,3), 256, GSMEM>>>(ah,am, wh+OFF_WV2,wm+OFF_WV2,
        nullptr, nullptr, nullptr, v8, CTOK, DDIM, CTXD, d2v, CTXN);
    sim8_kernel<<<dim3(2,16,BB*HH), 256>>>(q8, k8, sim, CTXN, d2q, d2k);
    softmax_quant<<<BB*HH*NN, 128>>>(sim, w8, CTXN, 128, d2w);
    av8_kernel<<<dim3(16,BB*HH), 256>>>(w8, v8, ah, am, CTXN, 128, d2w, d2v);
    hgemm<1,false><<<dim3(8,32), 256, GSMEM>>>(ah,am, wh+OFF_WO2,wm+OFF_WO2,
        a2bo, out, out, nullptr, TOK, DDIM, DDIM, nullptr, 0);

    // ---- GEGLU FF ----
    ln_kernel<<<TOK, 256>>>(out, n3w, n3b, ah, am);
    hgemm<2,false><<<dim3(64,32), 256, GSMEM>>>(ah,am, wh+OFF_FF1,wm+OFF_FF1,
        ffb1, nullptr, hbuf, nullptr, TOK, FFIN, DDIM, nullptr, 0);
    geglu_kernel<<<(TOK*(FFHID/4))/256, 256>>>(hbuf, ah, am);
    hgemm<1,false><<<dim3(8,32), 256, GSMEM>>>(ah,am, wh+OFF_FF2,wm+OFF_FF2,
        ffb2, out, out, nullptr, TOK, DDIM, FFHID, nullptr, 0);
}

// round 9
// speedup vs baseline: 2.3104x; 1.2205x over previous
#include <cuda_runtime.h>
#include <cuda_fp16.h>
#include <math.h>
#include <stdint.h>

// ---------------- problem constants ----------------
#define BB 4
#define NN 1024
#define DDIM 1024
#define HH 16
#define CTXN 77
#define CTXD 768
#define FFIN 8192
#define FFHID 4096
#define TOK (BB*NN)      // 4096
#define CTOK (BB*CTXN)   // 308
#define SCALE 0.125f
#define RSC 2048.0f      // residual plane scale (2^11)
#define RSCINV (1.0f/2048.0f)
#define QKVSTRIDE ((size_t)TOK*DDIM)

// ---------------- scratch (device globals) ----------------
__device__ char  g_qkv8[(size_t)3*TOK*DDIM];     // q8 | k8 | v8, each [b,h,n,64]
__device__ unsigned char g_w8[(size_t)BB*HH*NN*NN];
__device__ float g_sim[(size_t)BB*HH*NN*NN];     // scores; reused for FF hidden

// activation half-split planes (max 4096x4096)
#define AMAX ((size_t)TOK*FFHID)
__device__ __half g_ah[AMAX];
__device__ __half g_am[AMAX];

// weight split planes, concatenated [N,K] layouts
#define OFF_WQ1  ((size_t)0)
#define OFF_WK1  ((size_t)1048576)
#define OFF_WV1  ((size_t)2097152)
#define OFF_WO1  ((size_t)3145728)
#define OFF_WQ2  ((size_t)4194304)
#define OFF_WO2  ((size_t)5242880)
#define OFF_WK2  ((size_t)6291456)
#define OFF_WV2  ((size_t)(6291456+786432))
#define OFF_FF1  ((size_t)(6291456+1572864))
#define OFF_FF2  ((size_t)(OFF_FF1+8388608))
#define WTOT     ((size_t)(OFF_FF2+4194304))
__device__ __half g_wh[WTOT];
__device__ __half g_wm[WTOT];

// ---------------- helpers ----------------
__device__ __forceinline__ uint32_t smem_u32(const void* p) {
    uint32_t a;
    asm("{ .reg .u64 t; cvta.to.shared.u64 t, %1; cvt.u32.u64 %0, t; }" : "=r"(a) : "l"(p));
    return a;
}
__device__ __forceinline__ void cpasync16(uint32_t s, const void* g, int sz) {
    asm volatile("cp.async.cg.shared.global [%0], [%1], 16, %2;"
                 :: "r"(s), "l"(g), "r"(sz));
}
__device__ __forceinline__ void cpcommit() { asm volatile("cp.async.commit_group;"); }
__device__ __forceinline__ void cpwait2()  { asm volatile("cp.async.wait_group 2;"); }

// scaled split: x ~= h + m/2048, with m in fp16 normal range
__device__ __forceinline__ void split2(float x, __half& h, __half& m) {
    h = __float2half_rn(x);
    m = __float2half_rn((x - __half2float(h)) * RSC);
}

// ---------------- LayerNorm -> (h,m) planes ----------------
__global__ void __launch_bounds__(256) ln_kernel(const float* __restrict__ x,
    const float* __restrict__ w, const float* __restrict__ b,
    __half* __restrict__ H, __half* __restrict__ Mp)
{
    int row = blockIdx.x;
    int t = threadIdx.x;
    const float4* xr = (const float4*)(x + (size_t)row * DDIM);
    float4 v = xr[t];
    float s  = v.x + v.y + v.z + v.w;
    float ss = v.x*v.x + v.y*v.y + v.z*v.z + v.w*v.w;
    #pragma unroll
    for (int o = 16; o; o >>= 1) {
        s  += __shfl_xor_sync(0xffffffffu, s, o);
        ss += __shfl_xor_sync(0xffffffffu, ss, o);
    }
    __shared__ float sh_s[8], sh_q[8];
    int wid = t >> 5, lane = t & 31;
    if (lane == 0) { sh_s[wid] = s; sh_q[wid] = ss; }
    __syncthreads();
    if (t == 0) {
        float a = 0.f, c = 0.f;
        #pragma unroll
        for (int i = 0; i < 8; i++) { a += sh_s[i]; c += sh_q[i]; }
        float m = a * (1.0f/DDIM);
        float var = c * (1.0f/DDIM) - m*m;
        sh_s[0] = m;
        sh_q[0] = rsqrtf(var + 1e-5f);
    }
    __syncthreads();
    float m = sh_s[0], r = sh_q[0];
    float4 wv = ((const float4*)w)[t];
    float4 bv = ((const float4*)b)[t];
    float o[4];
    o[0] = (v.x - m) * r * wv.x + bv.x;
    o[1] = (v.y - m) * r * wv.y + bv.y;
    o[2] = (v.z - m) * r * wv.z + bv.z;
    o[3] = (v.w - m) * r * wv.w + bv.w;
    ushort4 uh, um;
    __half h0, m0;
    split2(o[0], h0, m0); uh.x = __half_as_ushort(h0); um.x = __half_as_ushort(m0);
    split2(o[1], h0, m0); uh.y = __half_as_ushort(h0); um.y = __half_as_ushort(m0);
    split2(o[2], h0, m0); uh.z = __half_as_ushort(h0); um.z = __half_as_ushort(m0);
    split2(o[3], h0, m0); uh.w = __half_as_ushort(h0); um.w = __half_as_ushort(m0);
    ((ushort4*)(H  + (size_t)row * DDIM))[t] = uh;
    ((ushort4*)(Mp + (size_t)row * DDIM))[t] = um;
}

// ---------------- activation split (ctx only) ----------------
__global__ void __launch_bounds__(256) asplit_k(const float* __restrict__ A,
    __half* __restrict__ H, __half* __restrict__ Mp, int n4)
{
    int i = blockIdx.x * 256 + threadIdx.x;
    if (i >= n4) return;
    float4 v = ((const float4*)A)[i];
    ushort4 uh, um;
    __half h0, m0;
    split2(v.x, h0, m0); uh.x = __half_as_ushort(h0); um.x = __half_as_ushort(m0);
    split2(v.y, h0, m0); uh.y = __half_as_ushort(h0); um.y = __half_as_ushort(m0);
    split2(v.z, h0, m0); uh.z = __half_as_ushort(h0); um.z = __half_as_ushort(m0);
    split2(v.w, h0, m0); uh.w = __half_as_ushort(h0); um.w = __half_as_ushort(m0);
    ((ushort4*)H)[i] = uh; ((ushort4*)Mp)[i] = um;
}

// ---------------- weight transpose+split (batched) ----------------
struct WS6 { const float* w[6]; };

__device__ __forceinline__ void wsplit_body(const float* __restrict__ W,
    __half* __restrict__ H, __half* __restrict__ Mp, int K, int N)
{
    __shared__ float tile[32][33];
    int n0 = blockIdx.x * 32, k0 = blockIdx.y * 32;
    int tx = threadIdx.x & 31, ty = threadIdx.x >> 5;
    #pragma unroll
    for (int i = 0; i < 4; i++)
        tile[ty + i*8][tx] = W[(size_t)(k0 + ty + i*8) * N + n0 + tx];
    __syncthreads();
    #pragma unroll
    for (int i = 0; i < 4; i++) {
        int nl = ty + i*8;
        float x = tile[tx][nl];
        __half h, m;
        split2(x, h, m);
        size_t o = (size_t)(n0 + nl) * K + k0 + tx;
        H[o] = h; Mp[o] = m;
    }
}

__global__ void __launch_bounds__(256) wsplit6_k(WS6 ws,
    __half* __restrict__ H, __half* __restrict__ Mp)
{
    int z = blockIdx.z;
    size_t off = (size_t)z * 1048576;
    wsplit_body(ws.w[z], H + off, Mp + off, DDIM, DDIM);
}

__global__ void __launch_bounds__(256) wsplit_ctx2_k(const float* __restrict__ wk,
    const float* __restrict__ wv, __half* __restrict__ H, __half* __restrict__ Mp)
{
    int z = blockIdx.z;
    const float* W = z ? wv : wk;
    size_t off = OFF_WK2 + (size_t)z * 786432;
    wsplit_body(W, H + off, Mp + off, CTXD, DDIM);
}

__global__ void __launch_bounds__(256) wsplit1_k(const float* __restrict__ W,
    __half* __restrict__ H, __half* __restrict__ Mp, int K, int N)
{
    wsplit_body(W, H, Mp, K, N);
}

// ---------------- HMMA GEMM: D[M,N] = A[M,K] @ T[N,K]^T, fp16 split --------
// Dual accumulators: mma tile-acc flushed into fp32 master (RN FADD) every 2
// iterations to break tensor-core RZ accumulation bias.
// TERMS=3: (h,m'), (m',h) [scaled] -> rescale -> (h,h)   (quantizer-bound outputs)
// TERMS=2: (m',h) [scaled] -> rescale -> (h,h)           (smooth outputs only)
// MODE 0: fake-quant -> int8 [buf][b,h,n,64] (buf = head>>4, fused qkv demux)
// MODE 1: +bias+res fp32 ; MODE 2: +bias fp32
#define BM 128
#define BN 128
#define BK 32
#define ROWB 80
#define ATILE (BM*ROWB)
#define STAGEB (2*ATILE)
#define NSTAGE 4
#define GSMEM (NSTAGE*STAGEB)

template<int MODE, bool BOUNDS, int TERMS>
__global__ void __launch_bounds__(256, 1) hgemm(
    const __half* __restrict__ Ah, const __half* __restrict__ Am,
    const __half* __restrict__ Bh, const __half* __restrict__ Bm,
    const float* __restrict__ bias, const float* __restrict__ res,
    float* __restrict__ Cf, char* __restrict__ Cq,
    int M, int N, int K, const float* __restrict__ dptr, int rows_per_b)
{
    extern __shared__ char smem[];
    const uint32_t sb = smem_u32(smem);
    const int tid  = threadIdx.x;
    const int wid  = tid >> 5;
    const int lane = tid & 31;
    const int m0 = blockIdx.y * BM;
    const int n0 = blockIdx.x * BN;
    const int wrow = (wid >> 2) * 64;
    const int wcol = (wid & 3) * 32;

    const int KT32 = K >> 5;
    const int T = TERMS * KT32;   // even for our shapes

    const __half* APL[3];
    const __half* BPL[3];
    if (TERMS == 3) {
        APL[0]=Ah; BPL[0]=Bm;
        APL[1]=Am; BPL[1]=Bh;
        APL[2]=Ah; BPL[2]=Bh;
    } else {
        APL[0]=Am; BPL[0]=Bh;
        APL[1]=Ah; BPL[1]=Bh;
        APL[2]=Ah; BPL[2]=Bh;
    }

    int lkt = 0, lterm = 0;
    const __half* lpa = APL[0];
    const __half* lpb = BPL[0];

    const int arow = tid >> 1;
    const int aco  = (tid & 1) * 32;
    int grow = m0 + arow;
    if (BOUNDS && grow >= M) grow = M - 1;
    const int asz = (!BOUNDS || (m0 + arow) < M) ? 16 : 0;

    auto issue = [&](int buf) {
        const char* ga = (const char*)lpa + (((size_t)grow*K + lkt*BK) << 1) + aco;
        uint32_t sa = sb + buf*STAGEB + arow*ROWB + aco;
        cpasync16(sa,      ga,      asz);
        cpasync16(sa + 16, ga + 16, asz);
        const char* gb = (const char*)lpb + (((size_t)(n0+arow)*K + lkt*BK) << 1) + aco;
        uint32_t sbb = sb + buf*STAGEB + ATILE + arow*ROWB + aco;
        cpasync16(sbb,      gb,      16);
        cpasync16(sbb + 16, gb + 16, 16);
    };
    auto adv = [&]() {
        if (++lkt == KT32) {
            lkt = 0;
            ++lterm;
            int tt = lterm < TERMS ? lterm : TERMS-1;
            lpa = APL[tt];
            lpb = BPL[tt];
        }
    };

    float acc[4][4][4];    // mma tile accumulator (short RZ chains)
    float accm[4][4][4];   // fp32 master accumulator (RN adds)
    #pragma unroll
    for (int i = 0; i < 4; i++)
        #pragma unroll
        for (int j = 0; j < 4; j++)
            #pragma unroll
            for (int r = 0; r < 4; r++) { acc[i][j][r] = 0.f; accm[i][j][r] = 0.f; }

    issue(0); adv(); cpcommit();
    issue(1); adv(); cpcommit();

    const int rescIt = (TERMS == 3) ? 2*KT32 : KT32;

    for (int it = 0; it < T; it++) {
        if (it + 2 < T) { issue((it + 2) % NSTAGE); adv(); }
        cpcommit();
        cpwait2();
        __syncthreads();
        if (it == rescIt) {
            #pragma unroll
            for (int i = 0; i < 4; i++)
                #pragma unroll
                for (int j = 0; j < 4; j++)
                    #pragma unroll
                    for (int r = 0; r < 4; r++) accm[i][j][r] *= RSCINV;
        }
        const uint32_t abase = sb + (it % NSTAGE) * STAGEB;
        const uint32_t bbase = abase + ATILE;
        #pragma unroll
        for (int kh = 0; kh < 2; kh++) {
            uint32_t b0[4], b1[4];
            #pragma unroll
            for (int nt = 0; nt < 4; nt++) {
                uint32_t ad = bbase + (wcol + nt*8 + (lane & 7))*ROWB
                            + kh*32 + ((lane >> 3) & 1)*16;
                asm volatile("ldmatrix.sync.aligned.m8n8.x2.shared.b16 {%0,%1}, [%2];"
                             : "=r"(b0[nt]), "=r"(b1[nt]) : "r"(ad));
            }
            #pragma unroll
            for (int mt = 0; mt < 4; mt++) {
                uint32_t a0, a1, a2, a3;
                uint32_t ad = abase + (wrow + mt*16 + ((lane >> 3) & 1)*8 + (lane & 7))*ROWB
                            + kh*32 + ((lane >> 4) & 1)*16;
                asm volatile("ldmatrix.sync.aligned.m8n8.x4.shared.b16 {%0,%1,%2,%3}, [%4];"
                             : "=r"(a0), "=r"(a1), "=r"(a2), "=r"(a3) : "r"(ad));
                #pragma unroll
                for (int nt = 0; nt < 4; nt++) {
                    asm volatile(
                        "mma.sync.aligned.m16n8k16.row.col.f32.f16.f16.f32 "
                        "{%0,%1,%2,%3}, {%4,%5,%6,%7}, {%8,%9}, {%0,%1,%2,%3};"
                        : "+f"(acc[mt][nt][0]), "+f"(acc[mt][nt][1]),
                          "+f"(acc[mt][nt][2]), "+f"(acc[mt][nt][3])
                        : "r"(a0), "r"(a1), "r"(a2), "r"(a3), "r"(b0[nt]), "r"(b1[nt]));
                }
            }
        }
        if (it & 1) {
            #pragma unroll
            for (int i = 0; i < 4; i++)
                #pragma unroll
                for (int j = 0; j < 4; j++)
                    #pragma unroll
                    for (int r = 0; r < 4; r++) {
                        accm[i][j][r] += acc[i][j][r];
                        acc[i][j][r] = 0.f;
                    }
        }
    }

    // ---------------- epilogue ----------------
    float d = 0.f, invd = 0.f;
    if (MODE == 0) { d = *dptr; invd = 1.0f / d; }
    #pragma unroll
    for (int mt = 0; mt < 4; mt++) {
        int r0 = m0 + wrow + mt*16 + (lane >> 2);
        #pragma unroll
        for (int nt = 0; nt < 4; nt++) {
            int nc = n0 + wcol + nt*8 + (lane & 3)*2;
            #pragma unroll
            for (int hrow = 0; hrow < 2; hrow++) {
                int rr = r0 + hrow*8;
                if (BOUNDS && rr >= M) continue;
                float c0 = accm[mt][nt][hrow*2+0];
                float c1 = accm[mt][nt][hrow*2+1];
                if (MODE == 0) {
                    int hg = nc >> 6;            // global head across fused buffers
                    int buf = hg >> 4;           // 0=q, 1=k, 2=v (or subset)
                    int hl  = hg & 15;
                    int dd  = nc & 63;
                    int b = rr / rows_per_b;
                    int n = rr - b * rows_per_b;
                    char2 pk;
                    pk.x = (char)(int)fminf(fmaxf(rintf(c0 * invd), -128.f), 127.f);
                    pk.y = (char)(int)fminf(fmaxf(rintf(c1 * invd), -128.f), 127.f);
                    *(char2*)(Cq + (size_t)buf*QKVSTRIDE
                              + ((size_t)(b*HH + hl)*rows_per_b + n)*64 + dd) = pk;
                } else {
                    size_t off = (size_t)rr * N + nc;
                    float2 o;
                    o.x = c0 + bias[nc];
                    o.y = c1 + bias[nc+1];
                    if (MODE == 1) {
                        float2 rv = *(const float2*)(res + off);
                        o.x += rv.x; o.y += rv.y;
                    }
                    *(float2*)(Cf + off) = o;
                }
            }
        }
    }
}

// ---------------- int8 scores ----------------
__global__ void __launch_bounds__(256) sim8_kernel(
    const char* __restrict__ Q8, const char* __restrict__ K8,
    float* __restrict__ S, int nk,
    const float* __restrict__ dq, const float* __restrict__ dk)
{
    int bh = blockIdx.z;
    int i0 = blockIdx.y * 64;
    int j0 = blockIdx.x * 64;
    __shared__ int qs[16][68];
    __shared__ int ks[16][68];
    int tid = threadIdx.x;
    int row = tid >> 2;
    int c4  = (tid & 3) * 4;
    {
        int4 qv = *(const int4*)(Q8 + ((size_t)bh*NN + i0 + row)*64 + c4*4);
        qs[c4+0][row]=qv.x; qs[c4+1][row]=qv.y; qs[c4+2][row]=qv.z; qs[c4+3][row]=qv.w;
        int jr = j0 + row;
        int4 kv = make_int4(0,0,0,0);
        if (jr < nk) kv = *(const int4*)(K8 + ((size_t)bh*nk + jr)*64 + c4*4);
        ks[c4+0][row]=kv.x; ks[c4+1][row]=kv.y; ks[c4+2][row]=kv.z; ks[c4+3][row]=kv.w;
    }
    __syncthreads();
    int ty = tid >> 4, tx = tid & 15;
    int acc[4][4];
    #pragma unroll
    for (int i = 0; i < 4; i++)
        #pragma unroll
        for (int j = 0; j < 4; j++) acc[i][j] = 0;
    #pragma unroll
    for (int kk = 0; kk < 16; kk++) {
        int a[4], b[4];
        *(int4*)a = *(const int4*)&qs[kk][ty*4];
        *(int4*)b = *(const int4*)&ks[kk][tx*4];
        #pragma unroll
        for (int i = 0; i < 4; i++)
            #pragma unroll
            for (int j = 0; j < 4; j++) acc[i][j] = __dp4a(a[i], b[j], acc[i][j]);
    }
    float sc = dq[0] * dk[0] * SCALE;
    #pragma unroll
    for (int i = 0; i < 4; i++) {
        size_t ro = ((size_t)bh*NN + i0 + ty*4 + i) * nk;
        #pragma unroll
        for (int j = 0; j < 4; j++) {
            int jj = j0 + tx*4 + j;
            if (jj < nk) S[ro + jj] = (float)acc[i][j] * sc;
        }
    }
}

// ---------------- softmax + weight quant ----------------
__global__ void __launch_bounds__(128) softmax_quant(
    const float* __restrict__ S, unsigned char* __restrict__ W8,
    int cols, int colsp, const float* __restrict__ dptr)
{
    size_t row = blockIdx.x;
    const float* p = S + row * (size_t)cols;
    unsigned char* o = W8 + row * (size_t)colsp;
    int t = threadIdx.x;
    float buf[8];
    int nb = 0;
    float m = -INFINITY;
    for (int c = t; c < cols; c += 128) {
        float v = p[c];
        buf[nb++] = v;
        m = fmaxf(m, v);
    }
    #pragma unroll
    for (int off = 16; off; off >>= 1) m = fmaxf(m, __shfl_xor_sync(0xffffffffu, m, off));
    __shared__ float redm[4], reds[4];
    if ((t & 31) == 0) redm[t >> 5] = m;
    __syncthreads();
    m = fmaxf(fmaxf(redm[0], redm[1]), fmaxf(redm[2], redm[3]));
    float sum = 0.f;
    for (int i = 0; i < nb; i++) { buf[i] = expf(buf[i] - m); sum += buf[i]; }
    #pragma unroll
    for (int off = 16; off; off >>= 1) sum += __shfl_xor_sync(0xffffffffu, sum, off);
    if ((t & 31) == 0) reds[t >> 5] = sum;
    __syncthreads();
    sum = reds[0] + reds[1] + reds[2] + reds[3];
    float inv = 1.0f / sum;
    float invd = 1.0f / dptr[0];
    nb = 0;
    for (int c = t; c < colsp; c += 128) {
        unsigned char ob = 0;
        if (c < cols) {
            float q = rintf(buf[nb++] * inv * invd);
            ob = (unsigned char)(int)fminf(fmaxf(q, 0.f), 255.f);
        }
        o[c] = ob;
    }
}

// ---------------- AV (u8 x s8 dp4a) -> (h,m) planes ----------------
__global__ void __launch_bounds__(256) av8_kernel(
    const unsigned char* __restrict__ W8, const char* __restrict__ V8,
    __half* __restrict__ OH, __half* __restrict__ OM, int nk, int colsp,
    const float* __restrict__ dw, const float* __restrict__ dv)
{
    int bh = blockIdx.y; int b = bh >> 4; int h = bh & 15;
    int i0 = blockIdx.x * 64;
    __shared__ int ws[64][20];
    __shared__ unsigned char vtb[64][76];
    int tid = threadIdx.x;
    int row = tid >> 2;
    int c16 = (tid & 3) * 16;
    int ty = tid >> 4, tx = tid & 15;
    int acc[4][4];
    #pragma unroll
    for (int i = 0; i < 4; i++)
        #pragma unroll
        for (int d = 0; d < 4; d++) acc[i][d] = 0;

    const unsigned char* wb = W8 + ((size_t)bh*NN + i0 + row) * colsp + c16;
    const char* vb = V8 + ((size_t)bh*nk)*64;

    for (int j0 = 0; j0 < nk; j0 += 64) {
        uint4 wv = *(const uint4*)(wb + j0);
        *(uint4*)&ws[row][(tid & 3) * 4] = wv;
        int jr = j0 + row;
        int4 vv = make_int4(0,0,0,0);
        if (jr < nk) vv = *(const int4*)(vb + (size_t)jr*64 + c16);
        union { int4 v; unsigned char bb[16]; } u; u.v = vv;
        #pragma unroll
        for (int i = 0; i < 16; i++) vtb[c16 + i][row] = u.bb[i];
        __syncthreads();
        #pragma unroll
        for (int kk = 0; kk < 16; kk++) {
            int a[4], bb[4];
            #pragma unroll
            for (int i = 0; i < 4; i++) a[i] = ws[ty*4 + i][kk];
            #pragma unroll
            for (int d = 0; d < 4; d++) bb[d] = *(const int*)&vtb[tx*4 + d][kk*4];
            #pragma unroll
            for (int i = 0; i < 4; i++)
                #pragma unroll
                for (int d = 0; d < 4; d++)
                    asm("dp4a.u32.s32 %0, %1, %2, %3;"
                        : "=r"(acc[i][d]) : "r"(a[i]), "r"(bb[d]), "r"(acc[i][d]));
        }
        __syncthreads();
    }
    float sc = dw[0] * dv[0];
    #pragma unroll
    for (int i = 0; i < 4; i++) {
        size_t ro = ((size_t)(b*NN + i0 + ty*4 + i)) * DDIM + h*64 + tx*4;
        ushort4 uh, um;
        __half hh, mm;
        split2((float)acc[i][0] * sc, hh, mm); uh.x=__half_as_ushort(hh); um.x=__half_as_ushort(mm);
        split2((float)acc[i][1] * sc, hh, mm); uh.y=__half_as_ushort(hh); um.y=__half_as_ushort(mm);
        split2((float)acc[i][2] * sc, hh, mm); uh.z=__half_as_ushort(hh); um.z=__half_as_ushort(mm);
        split2((float)acc[i][3] * sc, hh, mm); uh.w=__half_as_ushort(hh); um.w=__half_as_ushort(mm);
        *(ushort4*)&OH[ro] = uh;
        *(ushort4*)&OM[ro] = um;
    }
}

// ---------------- GEGLU -> (h,m) planes ----------------
__global__ void __launch_bounds__(256) geglu_kernel(const float* __restrict__ h,
    __half* __restrict__ AH, __half* __restrict__ AM)
{
    size_t idx = (size_t)blockIdx.x * blockDim.x + threadIdx.x;
    size_t i  = idx / (FFHID / 4);
    size_t c4 = idx % (FFHID / 4);
    float4 a = *(const float4*)(h + i * FFIN + c4 * 4);
    float4 g = *(const float4*)(h + i * FFIN + FFHID + c4 * 4);
    const float kInvSqrt2 = 0.70710678118654752f;
    float o[4];
    o[0] = a.x * (0.5f * g.x * (1.f + erff(g.x * kInvSqrt2)));
    o[1] = a.y * (0.5f * g.y * (1.f + erff(g.y * kInvSqrt2)));
    o[2] = a.z * (0.5f * g.z * (1.f + erff(g.z * kInvSqrt2)));
    o[3] = a.w * (0.5f * g.w * (1.f + erff(g.w * kInvSqrt2)));
    ushort4 uh, um;
    __half hh, mm;
    split2(o[0], hh, mm); uh.x=__half_as_ushort(hh); um.x=__half_as_ushort(mm);
    split2(o[1], hh, mm); uh.y=__half_as_ushort(hh); um.y=__half_as_ushort(mm);
    split2(o[2], hh, mm); uh.z=__half_as_ushort(hh); um.z=__half_as_ushort(mm);
    split2(o[3], hh, mm); uh.w=__half_as_ushort(hh); um.w=__half_as_ushort(mm);
    ((ushort4*)AH)[idx] = uh;
    ((ushort4*)AM)[idx] = um;
}

// ---------------- launch ----------------
extern "C" void kernel_launch(void* const* d_in, const int* in_sizes, int n_in,
                              void* d_out, int out_size)
{
    const float* x    = (const float*)d_in[0];
    const float* ctx  = (const float*)d_in[1];
    const float* n1w  = (const float*)d_in[2];
    const float* n1b  = (const float*)d_in[3];
    const float* n2w  = (const float*)d_in[4];
    const float* n2b  = (const float*)d_in[5];
    const float* n3w  = (const float*)d_in[6];
    const float* n3b  = (const float*)d_in[7];
    const float* a1wq = (const float*)d_in[8];
    const float* a1wk = (const float*)d_in[9];
    const float* a1wv = (const float*)d_in[10];
    const float* a1wo = (const float*)d_in[11];
    const float* a1bo = (const float*)d_in[12];
    const float* a2wq = (const float*)d_in[13];
    const float* a2wk = (const float*)d_in[14];
    const float* a2wv = (const float*)d_in[15];
    const float* a2wo = (const float*)d_in[16];
    const float* a2bo = (const float*)d_in[17];
    const float* ffw1 = (const float*)d_in[18];
    const float* ffb1 = (const float*)d_in[19];
    const float* ffw2 = (const float*)d_in[20];
    const float* ffb2 = (const float*)d_in[21];
    const float* d1q  = (const float*)d_in[22];
    const float* d1k  = (const float*)d_in[23];
    const float* d1v  = (const float*)d_in[24];
    const float* d1w  = (const float*)d_in[25];
    const float* d2q  = (const float*)d_in[26];
    const float* d2k  = (const float*)d_in[27];
    const float* d2v  = (const float*)d_in[28];
    const float* d2w  = (const float*)d_in[29];
    float* out = (float*)d_out;

    float *sim;
    char *qkv8;
    unsigned char *w8;
    __half *ah, *am, *wh, *wm;
    cudaGetSymbolAddress((void**)&sim,  g_sim);
    cudaGetSymbolAddress((void**)&qkv8, g_qkv8);
    cudaGetSymbolAddress((void**)&w8,   g_w8);
    cudaGetSymbolAddress((void**)&ah,   g_ah);
    cudaGetSymbolAddress((void**)&am,   g_am);
    cudaGetSymbolAddress((void**)&wh,   g_wh);
    cudaGetSymbolAddress((void**)&wm,   g_wm);
    char* q8 = qkv8;
    char* k8 = qkv8 + QKVSTRIDE;
    char* v8 = qkv8 + 2*QKVSTRIDE;
    float* hbuf = sim;

    cudaFuncSetAttribute(hgemm<0,false,3>, cudaFuncAttributeMaxDynamicSharedMemorySize, GSMEM);
    cudaFuncSetAttribute(hgemm<0,true ,3>, cudaFuncAttributeMaxDynamicSharedMemorySize, GSMEM);
    cudaFuncSetAttribute(hgemm<1,false,3>, cudaFuncAttributeMaxDynamicSharedMemorySize, GSMEM);
    cudaFuncSetAttribute(hgemm<1,false,2>, cudaFuncAttributeMaxDynamicSharedMemorySize, GSMEM);
    cudaFuncSetAttribute(hgemm<2,false,2>, cudaFuncAttributeMaxDynamicSharedMemorySize, GSMEM);

    // ---- split all weights (batched; 4 launches) ----
    WS6 ws6;
    ws6.w[0] = a1wq; ws6.w[1] = a1wk; ws6.w[2] = a1wv;
    ws6.w[3] = a1wo; ws6.w[4] = a2wq; ws6.w[5] = a2wo;
    wsplit6_k<<<dim3(DDIM/32, DDIM/32, 6), 256>>>(ws6, wh, wm);
    wsplit_ctx2_k<<<dim3(DDIM/32, CTXD/32, 2), 256>>>(a2wk, a2wv, wh, wm);
    wsplit1_k<<<dim3(FFIN/32, DDIM/32), 256>>>(ffw1, wh+OFF_FF1, wm+OFF_FF1, DDIM, FFIN);
    wsplit1_k<<<dim3(DDIM/32, FFHID/32), 256>>>(ffw2, wh+OFF_FF2, wm+OFF_FF2, FFHID, DDIM);

    // ---- attn1 (self): fused QKV GEMM (N=3072, heads demuxed in epilogue) ----
    ln_kernel<<<TOK, 256>>>(x, n1w, n1b, ah, am);
    // NOTE: d1q==d1k==d1v numerically not guaranteed; but quant scale differs per output!
    // q uses d1q, k uses d1k, v uses d1v -> must pass per-head scale. Use three launches
    // ONLY if scales differ. They are separate tensors; handle via scale table below.
    hgemm<0,false,3><<<dim3(8,32), 256, GSMEM>>>(ah,am, wh+OFF_WQ1,wm+OFF_WQ1,
        nullptr, nullptr, nullptr, q8, TOK, DDIM, DDIM, d1q, NN);
    hgemm<0,false,3><<<dim3(8,32), 256, GSMEM>>>(ah,am, wh+OFF_WK1,wm+OFF_WK1,
        nullptr, nullptr, nullptr, k8, TOK, DDIM, DDIM, d1k, NN);
    hgemm<0,false,3><<<dim3(8,32), 256, GSMEM>>>(ah,am, wh+OFF_WV1,wm+OFF_WV1,
        nullptr, nullptr, nullptr, v8, TOK, DDIM, DDIM, d1v, NN);
    sim8_kernel<<<dim3(16,16,BB*HH), 256>>>(q8, k8, sim, NN, d1q, d1k);
    softmax_quant<<<BB*HH*NN, 128>>>(sim, w8, NN, NN, d1w);
    av8_kernel<<<dim3(16,BB*HH), 256>>>(w8, v8, ah, am, NN, NN, d1w, d1v);
    hgemm<1,false,3><<<dim3(8,32), 256, GSMEM>>>(ah,am, wh+OFF_WO1,wm+OFF_WO1,
        a1bo, x, out, nullptr, TOK, DDIM, DDIM, nullptr, 0);

    // ---- attn2 (cross) ----
    ln_kernel<<<TOK, 256>>>(out, n2w, n2b, ah, am);
    hgemm<0,false,3><<<dim3(8,32), 256, GSMEM>>>(ah,am, wh+OFF_WQ2,wm+OFF_WQ2,
        nullptr, nullptr, nullptr, q8, TOK, DDIM, DDIM, d2q, NN);
    asplit_k<<<(CTOK*CTXD/4 + 255)/256, 256>>>(ctx, ah, am, CTOK*CTXD/4);
    hgemm<0,true ,3><<<dim3(8,3), 256, GSMEM>>>(ah,am, wh+OFF_WK2,wm+OFF_WK2,
        nullptr, nullptr, nullptr, k8, CTOK, DDIM, CTXD, d2k, CTXN);
    hgemm<0,true ,3><<<dim3(8,3), 256, GSMEM>>>(ah,am, wh+OFF_WV2,wm+OFF_WV2,
        nullptr, nullptr, nullptr, v8, CTOK, DDIM, CTXD, d2v, CTXN);
    sim8_kernel<<<dim3(2,16,BB*HH), 256>>>(q8, k8, sim, CTXN, d2q, d2k);
    softmax_quant<<<BB*HH*NN, 128>>>(sim, w8, CTXN, 128, d2w);
    av8_kernel<<<dim3(16,BB*HH), 256>>>(w8, v8, ah, am, CTXN, 128, d2w, d2v);
    hgemm<1,false,2><<<dim3(8,32), 256, GSMEM>>>(ah,am, wh+OFF_WO2,wm+OFF_WO2,
        a2bo, out, out, nullptr, TOK, DDIM, DDIM, nullptr, 0);

    // ---- GEGLU FF ----
    ln_kernel<<<TOK, 256>>>(out, n3w, n3b, ah, am);
    hgemm<2,false,2><<<dim3(64,32), 256, GSMEM>>>(ah,am, wh+OFF_FF1,wm+OFF_FF1,
        ffb1, nullptr, hbuf, nullptr, TOK, FFIN, DDIM, nullptr, 0);
    geglu_kernel<<<(TOK*(FFHID/4))/256, 256>>>(hbuf, ah, am);
    hgemm<1,false,2><<<dim3(8,32), 256, GSMEM>>>(ah,am, wh+OFF_FF2,wm+OFF_FF2,
        ffb2, out, out, nullptr, TOK, DDIM, FFHID, nullptr, 0);
}